// round 4
// baseline (speedup 1.0000x reference)
#include <cuda_runtime.h>
#include <cuda_bf16.h>
#include <math.h>

// ---------------- problem constants ----------------
#define BATCH 2
#define C_IN 192
#define C3 576
#define HW 65536
#define IMG 256
#define HEADS 6
#define CH 32
#define WS 8
#define NTOK 64
#define NWIN 2048

__device__ float g_qkv1[(size_t)BATCH * C3 * HW];
__device__ float g_win[(size_t)3 * NWIN * HEADS * CH * NTOK];
__device__ float g_att[(size_t)BATCH * C_IN * HW];

// ---------------------------------------------------------------------------
// K1/K4: SGEMM  Y[o,p] = sum_c W[o,c] * X[c,p] (+bias), K=192.
// Tile: 64(o) x 128(p) x 16(k); 256 threads, 4x8 microtile, vectorized LDS.
// ---------------------------------------------------------------------------
__global__ __launch_bounds__(256) void k_gemm192(
    const float* __restrict__ Wt, const float* __restrict__ Xall,
    float* __restrict__ Yall, const float* __restrict__ bias, int M)
{
    const float* X = Xall + (size_t)blockIdx.z * C_IN * HW;
    float* Y = Yall + (size_t)blockIdx.z * (size_t)M * HW;
    const int oTile = blockIdx.y * 64;
    const int pTile = blockIdx.x * 128;

    __shared__ __align__(16) float Ws[16][68];
    __shared__ __align__(16) float Xs[16][128];

    const int tid = threadIdx.x;
    const int to = tid >> 4;    // 0..15 -> rows to*4..to*4+3
    const int tp = tid & 15;    // 0..15 -> cols tp*8..tp*8+7

    float acc[4][8];
#pragma unroll
    for (int i = 0; i < 4; i++)
#pragma unroll
        for (int j = 0; j < 8; j++) acc[i][j] = 0.f;

    const int wr = tid >> 2;        // 0..63  W row in tile
    const int wq = tid & 3;         // 0..3   k-quad

    for (int k0 = 0; k0 < 192; k0 += 16) {
        // W tile: 64 x 16, float4 along k, transposed store into Ws[k][o]
        {
            float4 w4 = *(const float4*)&Wt[(size_t)(oTile + wr) * 192 + k0 + wq * 4];
            Ws[wq * 4 + 0][wr] = w4.x;
            Ws[wq * 4 + 1][wr] = w4.y;
            Ws[wq * 4 + 2][wr] = w4.z;
            Ws[wq * 4 + 3][wr] = w4.w;
        }
        // X tile: 16 x 128, float4
#pragma unroll
        for (int it = 0; it < 2; it++) {
            int t = tid + it * 256;
            int r = t >> 5, c4 = (t & 31) * 4;
            *(float4*)&Xs[r][c4] = *(const float4*)&X[(size_t)(k0 + r) * HW + pTile + c4];
        }
        __syncthreads();
#pragma unroll
        for (int kk = 0; kk < 16; kk++) {
            float4 a4 = *(const float4*)&Ws[kk][to * 4];
            float4 b0 = *(const float4*)&Xs[kk][tp * 8];
            float4 b1 = *(const float4*)&Xs[kk][tp * 8 + 4];
            float a[4] = {a4.x, a4.y, a4.z, a4.w};
            float b[8] = {b0.x, b0.y, b0.z, b0.w, b1.x, b1.y, b1.z, b1.w};
#pragma unroll
            for (int i = 0; i < 4; i++)
#pragma unroll
                for (int j = 0; j < 8; j++)
                    acc[i][j] = fmaf(a[i], b[j], acc[i][j]);
        }
        __syncthreads();
    }

#pragma unroll
    for (int i = 0; i < 4; i++) {
        int o = oTile + to * 4 + i;
        float bs = bias ? bias[o] : 0.f;
        float4 r0 = make_float4(acc[i][0] + bs, acc[i][1] + bs, acc[i][2] + bs, acc[i][3] + bs);
        float4 r1 = make_float4(acc[i][4] + bs, acc[i][5] + bs, acc[i][6] + bs, acc[i][7] + bs);
        *(float4*)&Y[(size_t)o * HW + pTile + tp * 8] = r0;
        *(float4*)&Y[(size_t)o * HW + pTile + tp * 8 + 4] = r1;
    }
}

// ---------------------------------------------------------------------------
// K2: depthwise 3x3 (zero pad 1) + scatter into window layout
// ---------------------------------------------------------------------------
__global__ __launch_bounds__(256) void k_dwconv(
    const float* __restrict__ in, const float* __restrict__ wd,
    float* __restrict__ outWin)
{
    const int plane = blockIdx.z;
    const int b = plane / C3, ch3 = plane - b * C3;
    const int x0 = blockIdx.x * 32, y0 = blockIdx.y * 8;

    __shared__ float sm[10][34];
    const float* P = in + (size_t)plane * HW;
    const int tx = threadIdx.x, ty = threadIdx.y;
    const int lt = ty * 32 + tx;

    for (int e = lt; e < 340; e += 256) {
        int r = e / 34, cc = e - r * 34;
        int gy = y0 - 1 + r, gx = x0 - 1 + cc;
        float v = 0.f;
        if (gy >= 0 && gy < IMG && gx >= 0 && gx < IMG) v = P[gy * IMG + gx];
        sm[r][cc] = v;
    }
    __syncthreads();

    const float* wp = wd + ch3 * 9;
    float s = wp[0] * sm[ty + 0][tx + 0] + wp[1] * sm[ty + 0][tx + 1] + wp[2] * sm[ty + 0][tx + 2]
            + wp[3] * sm[ty + 1][tx + 0] + wp[4] * sm[ty + 1][tx + 1] + wp[5] * sm[ty + 1][tx + 2]
            + wp[6] * sm[ty + 2][tx + 0] + wp[7] * sm[ty + 2][tx + 1] + wp[8] * sm[ty + 2][tx + 2];

    const int h = y0 + ty, w = x0 + tx;
    const int z = ch3 / 192;
    const int head = (ch3 % 192) >> 5;
    const int c = ch3 & 31;
    const int win = b * 1024 + (h >> 3) * 32 + (w >> 3);
    const int tok = ((h & 7) << 3) + (w & 7);
    size_t dst = ((((size_t)z * NWIN + win) * HEADS + head) * CH + c) * NTOK + tok;
    outWin[dst] = s;
}

// ---------------------------------------------------------------------------
// K3: per (window, head) attention tile. 256 threads. Vectorized LDS layout:
//   qs[32][68], vs[32][68] (row-major, stride 68 for aligned float4)
//   ks_t[64][36] (K transposed: tok-major, conflict-free float4 over channel)
//   As[32][36], mwsT[64][68] (mlp_w transposed: x-major)
// ---------------------------------------------------------------------------
__global__ __launch_bounds__(256) void k_attn(
    const float* __restrict__ winBuf, const float* __restrict__ temperature,
    const float* __restrict__ mlp_w, const float* __restrict__ mlp_b,
    float* __restrict__ out)
{
    const int blk = blockIdx.x;          // winId*6 + head
    const int winId = blk / 6, head = blk - winId * 6;

    __shared__ __align__(16) float qs[32 * 68];
    __shared__ __align__(16) float ks_t[64 * 36];
    __shared__ __align__(16) float vs[32 * 68];
    __shared__ __align__(16) float As[32 * 36];
    __shared__ __align__(16) float mwsT[64 * 68];
    __shared__ float mbs[64];

    const int tid = threadIdx.x;
    const size_t base = (size_t)blk * (CH * NTOK);
    const size_t zs = (size_t)NWIN * HEADS * CH * NTOK;

    for (int e = tid; e < CH * NTOK; e += 256) {
        int r = e >> 6, c = e & 63;
        qs[r * 68 + c] = winBuf[base + e];
        ks_t[c * 36 + r] = winBuf[zs + base + e];
        vs[r * 68 + c] = winBuf[2 * zs + base + e];
    }
    for (int e = tid; e < 4096; e += 256) {
        int y = e >> 6, x = e & 63;
        mwsT[x * 68 + y] = mlp_w[e];
    }
    if (tid < 64) mbs[tid] = mlp_b[tid];
    __syncthreads();

    // ---- l2 normalize rows of q (row-major) and k (stored transposed) ----
    {
        int r = tid >> 2;
        int sub = tid & 3;
        float ss = 0.f;
        if (r < 32) {
            float* rowp = qs + r * 68 + sub * 16;
#pragma unroll
            for (int i = 0; i < 16; i++) { float v = rowp[i]; ss += v * v; }
            ss += __shfl_xor_sync(0xffffffffu, ss, 1);
            ss += __shfl_xor_sync(0xffffffffu, ss, 2);
            float inv = 1.0f / fmaxf(sqrtf(ss), 1e-12f);
#pragma unroll
            for (int i = 0; i < 16; i++) rowp[i] *= inv;
        } else {
            int d = r - 32;
#pragma unroll
            for (int i = 0; i < 16; i++) {
                float v = ks_t[(sub * 16 + i) * 36 + d];
                ss += v * v;
            }
            ss += __shfl_xor_sync(0xffffffffu, ss, 1);
            ss += __shfl_xor_sync(0xffffffffu, ss, 2);
            float inv = 1.0f / fmaxf(sqrtf(ss), 1e-12f);
#pragma unroll
            for (int i = 0; i < 16; i++) ks_t[(sub * 16 + i) * 36 + d] *= inv;
        }
    }
    __syncthreads();

    const float temp = temperature[head];

    // ---- A = q k^T * temp : thread -> (c, d0..d0+3) ----
    {
        int c = tid >> 3, d0 = (tid & 7) * 4;
        float a0 = 0.f, a1 = 0.f, a2 = 0.f, a3 = 0.f;
#pragma unroll
        for (int x4 = 0; x4 < 64; x4 += 4) {
            float4 qv = *(const float4*)&qs[c * 68 + x4];
            float4 k0 = *(const float4*)&ks_t[(x4 + 0) * 36 + d0];
            float4 k1 = *(const float4*)&ks_t[(x4 + 1) * 36 + d0];
            float4 k2 = *(const float4*)&ks_t[(x4 + 2) * 36 + d0];
            float4 k3 = *(const float4*)&ks_t[(x4 + 3) * 36 + d0];
            a0 = fmaf(qv.x, k0.x, fmaf(qv.y, k1.x, fmaf(qv.z, k2.x, fmaf(qv.w, k3.x, a0))));
            a1 = fmaf(qv.x, k0.y, fmaf(qv.y, k1.y, fmaf(qv.z, k2.y, fmaf(qv.w, k3.y, a1))));
            a2 = fmaf(qv.x, k0.z, fmaf(qv.y, k1.z, fmaf(qv.z, k2.z, fmaf(qv.w, k3.z, a2))));
            a3 = fmaf(qv.x, k0.w, fmaf(qv.y, k1.w, fmaf(qv.z, k2.w, fmaf(qv.w, k3.w, a3))));
        }
        float4 r = make_float4(a0 * temp, a1 * temp, a2 * temp, a3 * temp);
        *(float4*)&As[c * 36 + d0] = r;
    }
    __syncthreads();

    // ---- softmax over rows of A ----
    {
        int r = tid >> 3, j0 = (tid & 7) * 4;
        float4 v4 = *(const float4*)&As[r * 36 + j0];
        float v[4] = {v4.x, v4.y, v4.z, v4.w};
        float m = fmaxf(fmaxf(v[0], v[1]), fmaxf(v[2], v[3]));
        m = fmaxf(m, __shfl_xor_sync(0xffffffffu, m, 1));
        m = fmaxf(m, __shfl_xor_sync(0xffffffffu, m, 2));
        m = fmaxf(m, __shfl_xor_sync(0xffffffffu, m, 4));
        float s = 0.f;
#pragma unroll
        for (int i = 0; i < 4; i++) { v[i] = __expf(v[i] - m); s += v[i]; }
        s += __shfl_xor_sync(0xffffffffu, s, 1);
        s += __shfl_xor_sync(0xffffffffu, s, 2);
        s += __shfl_xor_sync(0xffffffffu, s, 4);
        float inv = 1.0f / s;
        float4 w4 = make_float4(v[0] * inv, v[1] * inv, v[2] * inv, v[3] * inv);
        *(float4*)&As[r * 36 + j0] = w4;
    }
    __syncthreads();

    // ---- O = A @ v ; gate = gelu(v @ mlp_w^T + b) ; write O*gate ----
    {
        int c = tid >> 3, x0 = (tid & 7) * 8;
        float o[8], g[8];
#pragma unroll
        for (int xx = 0; xx < 8; xx++) { o[xx] = 0.f; g[xx] = mbs[x0 + xx]; }

#pragma unroll
        for (int d = 0; d < 32; d++) {
            float a = As[c * 36 + d];
            float4 v0 = *(const float4*)&vs[d * 68 + x0];
            float4 v1 = *(const float4*)&vs[d * 68 + x0 + 4];
            o[0] = fmaf(a, v0.x, o[0]); o[1] = fmaf(a, v0.y, o[1]);
            o[2] = fmaf(a, v0.z, o[2]); o[3] = fmaf(a, v0.w, o[3]);
            o[4] = fmaf(a, v1.x, o[4]); o[5] = fmaf(a, v1.y, o[5]);
            o[6] = fmaf(a, v1.z, o[6]); o[7] = fmaf(a, v1.w, o[7]);
        }
#pragma unroll
        for (int j = 0; j < 64; j++) {
            float vv = vs[c * 68 + j];
            float4 m0 = *(const float4*)&mwsT[j * 68 + x0];
            float4 m1 = *(const float4*)&mwsT[j * 68 + x0 + 4];
            g[0] = fmaf(vv, m0.x, g[0]); g[1] = fmaf(vv, m0.y, g[1]);
            g[2] = fmaf(vv, m0.z, g[2]); g[3] = fmaf(vv, m0.w, g[3]);
            g[4] = fmaf(vv, m1.x, g[4]); g[5] = fmaf(vv, m1.y, g[5]);
            g[6] = fmaf(vv, m1.z, g[6]); g[7] = fmaf(vv, m1.w, g[7]);
        }

        const int b = winId >> 10, rem = winId & 1023;
        const int h1 = rem >> 5, w1 = rem & 31;
        const int hh = x0 >> 3;
        const int h = h1 * 8 + hh;
        size_t outBase = (((size_t)b * C_IN + head * CH + c) * IMG + h) * IMG + w1 * 8;
#pragma unroll
        for (int xx = 0; xx < 8; xx++) {
            float x = g[xx];
            float ge = 0.5f * x * (1.0f + erff(x * 0.70710678118654752f));
            out[outBase + xx] = o[xx] * ge;
        }
    }
}

// ---------------------------------------------------------------------------
extern "C" void kernel_launch(void* const* d_in, const int* in_sizes, int n_in,
                              void* d_out, int out_size)
{
    const float* x           = (const float*)d_in[0];
    const float* w_qkv       = (const float*)d_in[1];
    const float* w_dw        = (const float*)d_in[2];
    const float* temperature = (const float*)d_in[3];
    const float* mlp_w       = (const float*)d_in[4];
    const float* mlp_b       = (const float*)d_in[5];
    const float* proj_w      = (const float*)d_in[6];
    const float* proj_b      = (const float*)d_in[7];
    float* out = (float*)d_out;

    float *qkv1, *winb, *att;
    cudaGetSymbolAddress((void**)&qkv1, g_qkv1);
    cudaGetSymbolAddress((void**)&winb, g_win);
    cudaGetSymbolAddress((void**)&att, g_att);

    k_gemm192<<<dim3(HW / 128, C3 / 64, BATCH), 256>>>(w_qkv, x, qkv1, nullptr, C3);
    k_dwconv<<<dim3(IMG / 32, IMG / 8, BATCH * C3), dim3(32, 8)>>>(qkv1, w_dw, winb);
    k_attn<<<NWIN * HEADS, 256>>>(winb, temperature, mlp_w, mlp_b, att);
    k_gemm192<<<dim3(HW / 128, C_IN / 64, BATCH), 256>>>(proj_w, att, out, proj_b, C_IN);
}

// round 5
// speedup vs baseline: 1.1279x; 1.1279x over previous
#include <cuda_runtime.h>
#include <cuda_bf16.h>
#include <math.h>

// ---------------- problem constants ----------------
#define BATCH 2
#define C_IN 192
#define C3 576
#define HW 65536
#define IMG 256
#define HEADS 6
#define CH 32
#define WS 8
#define NTOK 64
#define NWIN 2048

__device__ float g_qkv1[(size_t)BATCH * C3 * HW];
__device__ float g_win[(size_t)3 * NWIN * HEADS * CH * NTOK];
__device__ float g_att[(size_t)BATCH * C_IN * HW];

// ---------------------------------------------------------------------------
// K1/K4: SGEMM  Y[o,p] = sum_c W[o,c] * X[c,p] (+bias), K=192.
// Tile: 64(o) x 256(p) x 16(k); 256 threads, 8x8 microtile.
// A-fragment loads are warp-broadcast (single address) -> crossbar traffic is
// dominated by B loads only: ~0.5 B/FMA << 1 B/FMA crossbar budget.
// ---------------------------------------------------------------------------
__global__ __launch_bounds__(256) void k_gemm192(
    const float* __restrict__ Wt, const float* __restrict__ Xall,
    float* __restrict__ Yall, const float* __restrict__ bias, int M)
{
    const float* X = Xall + (size_t)blockIdx.z * C_IN * HW;
    float* Y = Yall + (size_t)blockIdx.z * (size_t)M * HW;
    const int oTile = blockIdx.y * 64;
    const int pTile = blockIdx.x * 256;

    __shared__ __align__(16) float Ws[16][68];
    __shared__ __align__(16) float Xs[16][264];

    const int tid = threadIdx.x;
    const int to = tid >> 5;    // 0..7 -> rows to*8 .. to*8+7 (constant per warp)
    const int tp = tid & 31;    // 0..31 -> cols tp*8 .. tp*8+7

    float acc[8][8];
#pragma unroll
    for (int i = 0; i < 8; i++)
#pragma unroll
        for (int j = 0; j < 8; j++) acc[i][j] = 0.f;

    const int wrow = tid >> 2;      // 0..63
    const int wq = tid & 3;         // k-quad
    const int xr = tid >> 4;        // 0..15
    const int xc = (tid & 15) * 16; // 16 floats per thread

    for (int k0 = 0; k0 < 192; k0 += 16) {
        // W tile 64x16, transposed store
        {
            float4 w4 = *(const float4*)&Wt[(size_t)(oTile + wrow) * 192 + k0 + wq * 4];
            Ws[wq * 4 + 0][wrow] = w4.x;
            Ws[wq * 4 + 1][wrow] = w4.y;
            Ws[wq * 4 + 2][wrow] = w4.z;
            Ws[wq * 4 + 3][wrow] = w4.w;
        }
        // X tile 16x256
#pragma unroll
        for (int u = 0; u < 4; u++) {
            *(float4*)&Xs[xr][xc + u * 4] =
                *(const float4*)&X[(size_t)(k0 + xr) * HW + pTile + xc + u * 4];
        }
        __syncthreads();
#pragma unroll
        for (int kk = 0; kk < 16; kk++) {
            float4 a0 = *(const float4*)&Ws[kk][to * 8];
            float4 a1 = *(const float4*)&Ws[kk][to * 8 + 4];
            float4 b0 = *(const float4*)&Xs[kk][tp * 8];
            float4 b1 = *(const float4*)&Xs[kk][tp * 8 + 4];
            float a[8] = {a0.x, a0.y, a0.z, a0.w, a1.x, a1.y, a1.z, a1.w};
            float b[8] = {b0.x, b0.y, b0.z, b0.w, b1.x, b1.y, b1.z, b1.w};
#pragma unroll
            for (int i = 0; i < 8; i++)
#pragma unroll
                for (int j = 0; j < 8; j++)
                    acc[i][j] = fmaf(a[i], b[j], acc[i][j]);
        }
        __syncthreads();
    }

#pragma unroll
    for (int i = 0; i < 8; i++) {
        int o = oTile + to * 8 + i;
        float bs = bias ? bias[o] : 0.f;
        float4 r0 = make_float4(acc[i][0] + bs, acc[i][1] + bs, acc[i][2] + bs, acc[i][3] + bs);
        float4 r1 = make_float4(acc[i][4] + bs, acc[i][5] + bs, acc[i][6] + bs, acc[i][7] + bs);
        *(float4*)&Y[(size_t)o * HW + pTile + tp * 8] = r0;
        *(float4*)&Y[(size_t)o * HW + pTile + tp * 8 + 4] = r1;
    }
}

// ---------------------------------------------------------------------------
// K2: depthwise 3x3 (zero pad 1) + scatter into window layout
// ---------------------------------------------------------------------------
__global__ __launch_bounds__(256) void k_dwconv(
    const float* __restrict__ in, const float* __restrict__ wd,
    float* __restrict__ outWin)
{
    const int plane = blockIdx.z;
    const int b = plane / C3, ch3 = plane - b * C3;
    const int x0 = blockIdx.x * 32, y0 = blockIdx.y * 8;

    __shared__ float sm[10][34];
    const float* P = in + (size_t)plane * HW;
    const int tx = threadIdx.x, ty = threadIdx.y;
    const int lt = ty * 32 + tx;

    for (int e = lt; e < 340; e += 256) {
        int r = e / 34, cc = e - r * 34;
        int gy = y0 - 1 + r, gx = x0 - 1 + cc;
        float v = 0.f;
        if (gy >= 0 && gy < IMG && gx >= 0 && gx < IMG) v = P[gy * IMG + gx];
        sm[r][cc] = v;
    }
    __syncthreads();

    const float* wp = wd + ch3 * 9;
    float s = wp[0] * sm[ty + 0][tx + 0] + wp[1] * sm[ty + 0][tx + 1] + wp[2] * sm[ty + 0][tx + 2]
            + wp[3] * sm[ty + 1][tx + 0] + wp[4] * sm[ty + 1][tx + 1] + wp[5] * sm[ty + 1][tx + 2]
            + wp[6] * sm[ty + 2][tx + 0] + wp[7] * sm[ty + 2][tx + 1] + wp[8] * sm[ty + 2][tx + 2];

    const int h = y0 + ty, w = x0 + tx;
    const int z = ch3 / 192;
    const int head = (ch3 % 192) >> 5;
    const int c = ch3 & 31;
    const int win = b * 1024 + (h >> 3) * 32 + (w >> 3);
    const int tok = ((h & 7) << 3) + (w & 7);
    size_t dst = ((((size_t)z * NWIN + win) * HEADS + head) * CH + c) * NTOK + tok;
    outWin[dst] = s;
}

// ---------------------------------------------------------------------------
// K3: per (window, head) attention tile. 256 threads.
//   qs/ks/vs row-major [32][68]; QK^T with split 2x2 microtile (c,c+16)x(d,d+16)
//   -> q loads warp-broadcast, k loads only 2-way conflicted float4.
// ---------------------------------------------------------------------------
__global__ __launch_bounds__(256) void k_attn(
    const float* __restrict__ winBuf, const float* __restrict__ temperature,
    const float* __restrict__ mlp_w, const float* __restrict__ mlp_b,
    float* __restrict__ out)
{
    const int blk = blockIdx.x;          // winId*6 + head
    const int winId = blk / 6, head = blk - winId * 6;

    __shared__ __align__(16) float qs[32 * 68];
    __shared__ __align__(16) float ks[32 * 68];
    __shared__ __align__(16) float vs[32 * 68];
    __shared__ __align__(16) float As[32 * 36];
    __shared__ __align__(16) float mwsT[64 * 68];
    __shared__ float mbs[64];

    const int tid = threadIdx.x;
    const size_t base = (size_t)blk * (CH * NTOK);
    const size_t zs = (size_t)NWIN * HEADS * CH * NTOK;

    // vectorized loads: q/k/v tiles are contiguous 2048-float blocks
    for (int e = tid; e < 512; e += 256) {
        int r = e >> 4, c = (e & 15) * 4;
        *(float4*)&qs[r * 68 + c] = *(const float4*)&winBuf[base + (e << 2)];
        *(float4*)&ks[r * 68 + c] = *(const float4*)&winBuf[zs + base + (e << 2)];
        *(float4*)&vs[r * 68 + c] = *(const float4*)&winBuf[2 * zs + base + (e << 2)];
    }
    for (int e = tid; e < 1024; e += 256) {
        int y = e >> 4, x4 = (e & 15) * 4;
        float4 m = *(const float4*)&mlp_w[y * 64 + x4];
        mwsT[(x4 + 0) * 68 + y] = m.x;
        mwsT[(x4 + 1) * 68 + y] = m.y;
        mwsT[(x4 + 2) * 68 + y] = m.z;
        mwsT[(x4 + 3) * 68 + y] = m.w;
    }
    if (tid < 64) mbs[tid] = mlp_b[tid];
    __syncthreads();

    // ---- l2 normalize rows of q and k (64 rows, 4 threads/row) ----
    {
        int r = tid >> 2;
        int sub = tid & 3;
        float* rowp = (r < 32) ? (qs + r * 68) : (ks + (r - 32) * 68);
        rowp += sub * 16;
        float ss = 0.f;
#pragma unroll
        for (int i = 0; i < 16; i++) { float v = rowp[i]; ss += v * v; }
        ss += __shfl_xor_sync(0xffffffffu, ss, 1);
        ss += __shfl_xor_sync(0xffffffffu, ss, 2);
        float inv = 1.0f / fmaxf(sqrtf(ss), 1e-12f);
#pragma unroll
        for (int i = 0; i < 16; i++) rowp[i] *= inv;
    }
    __syncthreads();

    const float temp = temperature[head];

    // ---- A = q k^T * temp : split 2x2 microtile ----
    {
        const int c0 = tid >> 4, c1 = c0 + 16;     // c0 in 0..15
        const int d0 = tid & 15, d1 = d0 + 16;
        float a00 = 0.f, a01 = 0.f, a10 = 0.f, a11 = 0.f;
#pragma unroll
        for (int x4 = 0; x4 < 64; x4 += 4) {
            float4 q0 = *(const float4*)&qs[c0 * 68 + x4];
            float4 q1 = *(const float4*)&qs[c1 * 68 + x4];
            float4 k0 = *(const float4*)&ks[d0 * 68 + x4];
            float4 k1 = *(const float4*)&ks[d1 * 68 + x4];
            a00 = fmaf(q0.x, k0.x, fmaf(q0.y, k0.y, fmaf(q0.z, k0.z, fmaf(q0.w, k0.w, a00))));
            a01 = fmaf(q0.x, k1.x, fmaf(q0.y, k1.y, fmaf(q0.z, k1.z, fmaf(q0.w, k1.w, a01))));
            a10 = fmaf(q1.x, k0.x, fmaf(q1.y, k0.y, fmaf(q1.z, k0.z, fmaf(q1.w, k0.w, a10))));
            a11 = fmaf(q1.x, k1.x, fmaf(q1.y, k1.y, fmaf(q1.z, k1.z, fmaf(q1.w, k1.w, a11))));
        }
        As[c0 * 36 + d0] = a00 * temp;
        As[c0 * 36 + d1] = a01 * temp;
        As[c1 * 36 + d0] = a10 * temp;
        As[c1 * 36 + d1] = a11 * temp;
    }
    __syncthreads();

    // ---- softmax over rows of A ----
    {
        int r = tid >> 3, j0 = (tid & 7) * 4;
        float4 v4 = *(const float4*)&As[r * 36 + j0];
        float v[4] = {v4.x, v4.y, v4.z, v4.w};
        float m = fmaxf(fmaxf(v[0], v[1]), fmaxf(v[2], v[3]));
        m = fmaxf(m, __shfl_xor_sync(0xffffffffu, m, 1));
        m = fmaxf(m, __shfl_xor_sync(0xffffffffu, m, 2));
        m = fmaxf(m, __shfl_xor_sync(0xffffffffu, m, 4));
        float s = 0.f;
#pragma unroll
        for (int i = 0; i < 4; i++) { v[i] = __expf(v[i] - m); s += v[i]; }
        s += __shfl_xor_sync(0xffffffffu, s, 1);
        s += __shfl_xor_sync(0xffffffffu, s, 2);
        s += __shfl_xor_sync(0xffffffffu, s, 4);
        float inv = 1.0f / s;
        float4 w4 = make_float4(v[0] * inv, v[1] * inv, v[2] * inv, v[3] * inv);
        *(float4*)&As[r * 36 + j0] = w4;
    }
    __syncthreads();

    // ---- O = A @ v ; gate = gelu(v @ mlp_w^T + b) ; write O*gate ----
    {
        int c = tid >> 3, x0 = (tid & 7) * 8;
        float o[8], g[8];
#pragma unroll
        for (int xx = 0; xx < 8; xx++) { o[xx] = 0.f; g[xx] = mbs[x0 + xx]; }

#pragma unroll
        for (int d = 0; d < 32; d++) {
            float a = As[c * 36 + d];
            float4 v0 = *(const float4*)&vs[d * 68 + x0];
            float4 v1 = *(const float4*)&vs[d * 68 + x0 + 4];
            o[0] = fmaf(a, v0.x, o[0]); o[1] = fmaf(a, v0.y, o[1]);
            o[2] = fmaf(a, v0.z, o[2]); o[3] = fmaf(a, v0.w, o[3]);
            o[4] = fmaf(a, v1.x, o[4]); o[5] = fmaf(a, v1.y, o[5]);
            o[6] = fmaf(a, v1.z, o[6]); o[7] = fmaf(a, v1.w, o[7]);
        }
#pragma unroll
        for (int j = 0; j < 64; j++) {
            float vv = vs[c * 68 + j];
            float4 m0 = *(const float4*)&mwsT[j * 68 + x0];
            float4 m1 = *(const float4*)&mwsT[j * 68 + x0 + 4];
            g[0] = fmaf(vv, m0.x, g[0]); g[1] = fmaf(vv, m0.y, g[1]);
            g[2] = fmaf(vv, m0.z, g[2]); g[3] = fmaf(vv, m0.w, g[3]);
            g[4] = fmaf(vv, m1.x, g[4]); g[5] = fmaf(vv, m1.y, g[5]);
            g[6] = fmaf(vv, m1.z, g[6]); g[7] = fmaf(vv, m1.w, g[7]);
        }

        const int b = winId >> 10, rem = winId & 1023;
        const int h1 = rem >> 5, w1 = rem & 31;
        const int hh = x0 >> 3;
        const int h = h1 * 8 + hh;
        size_t outBase = (((size_t)b * C_IN + head * CH + c) * IMG + h) * IMG + w1 * 8;
#pragma unroll
        for (int xx = 0; xx < 8; xx++) {
            float x = g[xx];
            float ge = 0.5f * x * (1.0f + erff(x * 0.70710678118654752f));
            out[outBase + xx] = o[xx] * ge;
        }
    }
}

// ---------------------------------------------------------------------------
extern "C" void kernel_launch(void* const* d_in, const int* in_sizes, int n_in,
                              void* d_out, int out_size)
{
    const float* x           = (const float*)d_in[0];
    const float* w_qkv       = (const float*)d_in[1];
    const float* w_dw        = (const float*)d_in[2];
    const float* temperature = (const float*)d_in[3];
    const float* mlp_w       = (const float*)d_in[4];
    const float* mlp_b       = (const float*)d_in[5];
    const float* proj_w      = (const float*)d_in[6];
    const float* proj_b      = (const float*)d_in[7];
    float* out = (float*)d_out;

    float *qkv1, *winb, *att;
    cudaGetSymbolAddress((void**)&qkv1, g_qkv1);
    cudaGetSymbolAddress((void**)&winb, g_win);
    cudaGetSymbolAddress((void**)&att, g_att);

    k_gemm192<<<dim3(HW / 256, C3 / 64, BATCH), 256>>>(w_qkv, x, qkv1, nullptr, C3);
    k_dwconv<<<dim3(IMG / 32, IMG / 8, BATCH * C3), dim3(32, 8)>>>(qkv1, w_dw, winb);
    k_attn<<<NWIN * HEADS, 256>>>(winb, temperature, mlp_w, mlp_b, att);
    k_gemm192<<<dim3(HW / 256, C_IN / 64, BATCH), 256>>>(proj_w, att, out, proj_b, C_IN);
}

// round 6
// speedup vs baseline: 1.3667x; 1.2117x over previous
#include <cuda_runtime.h>
#include <cuda_bf16.h>
#include <math.h>
#include <stdint.h>

// ---------------- problem constants ----------------
#define BATCH 2
#define C_IN 192
#define C3 576
#define HW 65536
#define IMG 256
#define HEADS 6
#define CH 32
#define WS 8
#define NTOK 64
#define NWIN 2048

__device__ float g_qkv1[(size_t)BATCH * C3 * HW];
__device__ float g_win[(size_t)3 * NWIN * HEADS * CH * NTOK];
__device__ float g_att[(size_t)BATCH * C_IN * HW];

// ---------------------------------------------------------------------------
// bf16-split helpers: x = hi + lo, hi=bf16(x), lo=bf16(x-hi).
// Pair-packed into b32: low 16 bits = even-k element, high = odd-k element.
// ---------------------------------------------------------------------------
__device__ __forceinline__ void split2(float e0, float e1, uint32_t& hp, uint32_t& lp)
{
    __nv_bfloat16 h0 = __float2bfloat16(e0);
    __nv_bfloat16 h1 = __float2bfloat16(e1);
    __nv_bfloat16 l0 = __float2bfloat16(e0 - __bfloat162float(h0));
    __nv_bfloat16 l1 = __float2bfloat16(e1 - __bfloat162float(h1));
    __nv_bfloat162 hh; hh.x = h0; hh.y = h1;
    __nv_bfloat162 ll; ll.x = l0; ll.y = l1;
    hp = *reinterpret_cast<uint32_t*>(&hh);
    lp = *reinterpret_cast<uint32_t*>(&ll);
}

__device__ __forceinline__ void mma16816(float* d, const uint32_t* a, uint32_t b0, uint32_t b1)
{
    asm volatile(
        "mma.sync.aligned.m16n8k16.row.col.f32.bf16.bf16.f32 "
        "{%0,%1,%2,%3}, {%4,%5,%6,%7}, {%8,%9}, {%0,%1,%2,%3};"
        : "+f"(d[0]), "+f"(d[1]), "+f"(d[2]), "+f"(d[3])
        : "r"(a[0]), "r"(a[1]), "r"(a[2]), "r"(a[3]), "r"(b0), "r"(b1));
}

// ---------------------------------------------------------------------------
// K1/K4: GEMM Y[o,p] = sum_c W[o,c] * X[c,p] (+bias), K=192, via bf16-split MMA.
// CTA tile 64(M) x 128(N) x 32(K); 8 warps in 2x4; warp tile 32x32.
// smem holds pair-packed b32: Ws[o][k2] (A row-major), Xs[p][k2] (B col-major).
// ---------------------------------------------------------------------------
__global__ __launch_bounds__(256) void k_gemm_mma(
    const float* __restrict__ Wt, const float* __restrict__ Xall,
    float* __restrict__ Yall, const float* __restrict__ bias, int M)
{
    const float* X = Xall + (size_t)blockIdx.z * C_IN * HW;
    float* Y = Yall + (size_t)blockIdx.z * (size_t)M * HW;
    const int oTile = blockIdx.y * 64;
    const int pTile = blockIdx.x * 128;

    // [chunk(k16)][row][k2 (8 pairs) + pad]
    __shared__ uint32_t WsH[2][64][9], WsL[2][64][9];
    __shared__ uint32_t XsH[2][128][9], XsL[2][128][9];

    const int tid = threadIdx.x;
    const int lane = tid & 31;
    const int wid = tid >> 5;
    const int warpM = wid >> 2;     // 0..1
    const int warpN = wid & 3;      // 0..3
    const int gid = lane >> 2;      // 0..7
    const int tig = lane & 3;       // 0..3

    float acc[2][4][4];
#pragma unroll
    for (int im = 0; im < 2; im++)
#pragma unroll
        for (int jn = 0; jn < 4; jn++)
#pragma unroll
            for (int r = 0; r < 4; r++) acc[im][jn][r] = 0.f;

    const int wo = tid >> 2;            // 0..63 : W row in tile
    const int wsub = tid & 3;           // 0..3  : 8-k chunk
    const int xkp = tid >> 4;           // 0..15 : k-pair index (k = 2*xkp)
    const int xp0 = (tid & 15) * 8;     // 0..120: p group (8 cols)

    for (int k0 = 0; k0 < 192; k0 += 32) {
        // ---- load & convert W tile (64 x 32) ----
        {
            const float* wptr = &Wt[(size_t)(oTile + wo) * 192 + k0 + wsub * 8];
            float4 f0 = *(const float4*)wptr;
            float4 f1 = *(const float4*)(wptr + 4);
            float f[8] = {f0.x, f0.y, f0.z, f0.w, f1.x, f1.y, f1.z, f1.w};
#pragma unroll
            for (int j = 0; j < 4; j++) {
                uint32_t hp, lp;
                split2(f[2 * j], f[2 * j + 1], hp, lp);
                int kk2 = wsub * 4 + j;          // 0..15
                int ch = kk2 >> 3, cc = kk2 & 7;
                WsH[ch][wo][cc] = hp;
                WsL[ch][wo][cc] = lp;
            }
        }
        // ---- load & convert X tile (32 x 128), store transposed [p][k2] ----
        {
            const float* xr0 = &X[(size_t)(k0 + 2 * xkp) * HW + pTile + xp0];
            const float* xr1 = xr0 + HW;
            float4 a0 = *(const float4*)xr0;
            float4 a1 = *(const float4*)(xr0 + 4);
            float4 b0 = *(const float4*)xr1;
            float4 b1 = *(const float4*)(xr1 + 4);
            float fe[8] = {a0.x, a0.y, a0.z, a0.w, a1.x, a1.y, a1.z, a1.w};
            float fo[8] = {b0.x, b0.y, b0.z, b0.w, b1.x, b1.y, b1.z, b1.w};
            int ch = xkp >> 3, cc = xkp & 7;
#pragma unroll
            for (int n = 0; n < 8; n++) {
                uint32_t hp, lp;
                split2(fe[n], fo[n], hp, lp);
                XsH[ch][xp0 + n][cc] = hp;
                XsL[ch][xp0 + n][cc] = lp;
            }
        }
        __syncthreads();

#pragma unroll
        for (int ch = 0; ch < 2; ch++) {
            uint32_t Ah[2][4], Al[2][4];
#pragma unroll
            for (int im = 0; im < 2; im++) {
                int r0 = warpM * 32 + im * 16 + gid;
                Ah[im][0] = WsH[ch][r0][tig];
                Ah[im][1] = WsH[ch][r0 + 8][tig];
                Ah[im][2] = WsH[ch][r0][tig + 4];
                Ah[im][3] = WsH[ch][r0 + 8][tig + 4];
                Al[im][0] = WsL[ch][r0][tig];
                Al[im][1] = WsL[ch][r0 + 8][tig];
                Al[im][2] = WsL[ch][r0][tig + 4];
                Al[im][3] = WsL[ch][r0 + 8][tig + 4];
            }
#pragma unroll
            for (int jn = 0; jn < 4; jn++) {
                int col = warpN * 32 + jn * 8 + gid;
                uint32_t bh0 = XsH[ch][col][tig], bh1 = XsH[ch][col][tig + 4];
                uint32_t bl0 = XsL[ch][col][tig], bl1 = XsL[ch][col][tig + 4];
#pragma unroll
                for (int im = 0; im < 2; im++) {
                    mma16816(acc[im][jn], Al[im], bh0, bh1);
                    mma16816(acc[im][jn], Ah[im], bl0, bl1);
                    mma16816(acc[im][jn], Ah[im], bh0, bh1);
                }
            }
        }
        __syncthreads();
    }

    // ---- epilogue ----
#pragma unroll
    for (int im = 0; im < 2; im++) {
        int row = oTile + warpM * 32 + im * 16 + gid;
        float bs0 = bias ? bias[row] : 0.f;
        float bs1 = bias ? bias[row + 8] : 0.f;
#pragma unroll
        for (int jn = 0; jn < 4; jn++) {
            int col = pTile + warpN * 32 + jn * 8 + tig * 2;
            float2 r0 = make_float2(acc[im][jn][0] + bs0, acc[im][jn][1] + bs0);
            float2 r1 = make_float2(acc[im][jn][2] + bs1, acc[im][jn][3] + bs1);
            *(float2*)&Y[(size_t)row * HW + col] = r0;
            *(float2*)&Y[(size_t)(row + 8) * HW + col] = r1;
        }
    }
}

// ---------------------------------------------------------------------------
// K2: depthwise 3x3 (zero pad 1) + scatter into window layout
// ---------------------------------------------------------------------------
__global__ __launch_bounds__(256) void k_dwconv(
    const float* __restrict__ in, const float* __restrict__ wd,
    float* __restrict__ outWin)
{
    const int plane = blockIdx.z;
    const int b = plane / C3, ch3 = plane - b * C3;
    const int x0 = blockIdx.x * 32, y0 = blockIdx.y * 8;

    __shared__ float sm[10][34];
    const float* P = in + (size_t)plane * HW;
    const int tx = threadIdx.x, ty = threadIdx.y;
    const int lt = ty * 32 + tx;

    for (int e = lt; e < 340; e += 256) {
        int r = e / 34, cc = e - r * 34;
        int gy = y0 - 1 + r, gx = x0 - 1 + cc;
        float v = 0.f;
        if (gy >= 0 && gy < IMG && gx >= 0 && gx < IMG) v = P[gy * IMG + gx];
        sm[r][cc] = v;
    }
    __syncthreads();

    const float* wp = wd + ch3 * 9;
    float s = wp[0] * sm[ty + 0][tx + 0] + wp[1] * sm[ty + 0][tx + 1] + wp[2] * sm[ty + 0][tx + 2]
            + wp[3] * sm[ty + 1][tx + 0] + wp[4] * sm[ty + 1][tx + 1] + wp[5] * sm[ty + 1][tx + 2]
            + wp[6] * sm[ty + 2][tx + 0] + wp[7] * sm[ty + 2][tx + 1] + wp[8] * sm[ty + 2][tx + 2];

    const int h = y0 + ty, w = x0 + tx;
    const int z = ch3 / 192;
    const int head = (ch3 % 192) >> 5;
    const int c = ch3 & 31;
    const int win = b * 1024 + (h >> 3) * 32 + (w >> 3);
    const int tok = ((h & 7) << 3) + (w & 7);
    size_t dst = ((((size_t)z * NWIN + win) * HEADS + head) * CH + c) * NTOK + tok;
    outWin[dst] = s;
}

// ---------------------------------------------------------------------------
// K3: one block per WINDOW; loops over 6 heads, reusing the mlp_w smem tile.
// ---------------------------------------------------------------------------
__global__ __launch_bounds__(256) void k_attn(
    const float* __restrict__ winBuf, const float* __restrict__ temperature,
    const float* __restrict__ mlp_w, const float* __restrict__ mlp_b,
    float* __restrict__ out)
{
    const int winId = blockIdx.x;

    __shared__ __align__(16) float qs[32 * 68];
    __shared__ __align__(16) float ks[32 * 68];
    __shared__ __align__(16) float vs[32 * 68];
    __shared__ __align__(16) float As[32 * 36];
    __shared__ __align__(16) float mwsT[64 * 68];
    __shared__ float mbs[64];

    const int tid = threadIdx.x;
    const size_t zs = (size_t)NWIN * HEADS * CH * NTOK;

    for (int e = tid; e < 1024; e += 256) {
        int y = e >> 4, x4 = (e & 15) * 4;
        float4 m = *(const float4*)&mlp_w[y * 64 + x4];
        mwsT[(x4 + 0) * 68 + y] = m.x;
        mwsT[(x4 + 1) * 68 + y] = m.y;
        mwsT[(x4 + 2) * 68 + y] = m.z;
        mwsT[(x4 + 3) * 68 + y] = m.w;
    }
    if (tid < 64) mbs[tid] = mlp_b[tid];

    for (int head = 0; head < HEADS; head++) {
        const size_t base = (size_t)(winId * HEADS + head) * (CH * NTOK);
        __syncthreads();    // protects q/k/v reuse from previous head

        for (int e = tid; e < 512; e += 256) {
            int r = e >> 4, c = (e & 15) * 4;
            *(float4*)&qs[r * 68 + c] = *(const float4*)&winBuf[base + (e << 2)];
            *(float4*)&ks[r * 68 + c] = *(const float4*)&winBuf[zs + base + (e << 2)];
            *(float4*)&vs[r * 68 + c] = *(const float4*)&winBuf[2 * zs + base + (e << 2)];
        }
        __syncthreads();

        // ---- l2 normalize rows of q and k ----
        {
            int r = tid >> 2;
            int sub = tid & 3;
            float* rowp = (r < 32) ? (qs + r * 68) : (ks + (r - 32) * 68);
            rowp += sub * 16;
            float ss = 0.f;
#pragma unroll
            for (int i = 0; i < 16; i++) { float v = rowp[i]; ss += v * v; }
            ss += __shfl_xor_sync(0xffffffffu, ss, 1);
            ss += __shfl_xor_sync(0xffffffffu, ss, 2);
            float inv = 1.0f / fmaxf(sqrtf(ss), 1e-12f);
#pragma unroll
            for (int i = 0; i < 16; i++) rowp[i] *= inv;
        }
        __syncthreads();

        const float temp = temperature[head];

        // ---- A = q k^T * temp : split 2x2 microtile ----
        {
            const int c0 = tid >> 4, c1 = c0 + 16;
            const int d0 = tid & 15, d1 = d0 + 16;
            float a00 = 0.f, a01 = 0.f, a10 = 0.f, a11 = 0.f;
#pragma unroll
            for (int x4 = 0; x4 < 64; x4 += 4) {
                float4 q0 = *(const float4*)&qs[c0 * 68 + x4];
                float4 q1 = *(const float4*)&qs[c1 * 68 + x4];
                float4 k0 = *(const float4*)&ks[d0 * 68 + x4];
                float4 k1 = *(const float4*)&ks[d1 * 68 + x4];
                a00 = fmaf(q0.x, k0.x, fmaf(q0.y, k0.y, fmaf(q0.z, k0.z, fmaf(q0.w, k0.w, a00))));
                a01 = fmaf(q0.x, k1.x, fmaf(q0.y, k1.y, fmaf(q0.z, k1.z, fmaf(q0.w, k1.w, a01))));
                a10 = fmaf(q1.x, k0.x, fmaf(q1.y, k0.y, fmaf(q1.z, k0.z, fmaf(q1.w, k0.w, a10))));
                a11 = fmaf(q1.x, k1.x, fmaf(q1.y, k1.y, fmaf(q1.z, k1.z, fmaf(q1.w, k1.w, a11))));
            }
            As[c0 * 36 + d0] = a00 * temp;
            As[c0 * 36 + d1] = a01 * temp;
            As[c1 * 36 + d0] = a10 * temp;
            As[c1 * 36 + d1] = a11 * temp;
        }
        __syncthreads();

        // ---- softmax over rows of A ----
        {
            int r = tid >> 3, j0 = (tid & 7) * 4;
            float4 v4 = *(const float4*)&As[r * 36 + j0];
            float v[4] = {v4.x, v4.y, v4.z, v4.w};
            float m = fmaxf(fmaxf(v[0], v[1]), fmaxf(v[2], v[3]));
            m = fmaxf(m, __shfl_xor_sync(0xffffffffu, m, 1));
            m = fmaxf(m, __shfl_xor_sync(0xffffffffu, m, 2));
            m = fmaxf(m, __shfl_xor_sync(0xffffffffu, m, 4));
            float s = 0.f;
#pragma unroll
            for (int i = 0; i < 4; i++) { v[i] = __expf(v[i] - m); s += v[i]; }
            s += __shfl_xor_sync(0xffffffffu, s, 1);
            s += __shfl_xor_sync(0xffffffffu, s, 2);
            s += __shfl_xor_sync(0xffffffffu, s, 4);
            float inv = 1.0f / s;
            float4 w4 = make_float4(v[0] * inv, v[1] * inv, v[2] * inv, v[3] * inv);
            *(float4*)&As[r * 36 + j0] = w4;
        }
        __syncthreads();

        // ---- O = A @ v ; gate = gelu(v @ mlp_w^T + b) ; write O*gate ----
        {
            int c = tid >> 3, x0 = (tid & 7) * 8;
            float o[8], g[8];
#pragma unroll
            for (int xx = 0; xx < 8; xx++) { o[xx] = 0.f; g[xx] = mbs[x0 + xx]; }

#pragma unroll
            for (int d = 0; d < 32; d++) {
                float a = As[c * 36 + d];
                float4 v0 = *(const float4*)&vs[d * 68 + x0];
                float4 v1 = *(const float4*)&vs[d * 68 + x0 + 4];
                o[0] = fmaf(a, v0.x, o[0]); o[1] = fmaf(a, v0.y, o[1]);
                o[2] = fmaf(a, v0.z, o[2]); o[3] = fmaf(a, v0.w, o[3]);
                o[4] = fmaf(a, v1.x, o[4]); o[5] = fmaf(a, v1.y, o[5]);
                o[6] = fmaf(a, v1.z, o[6]); o[7] = fmaf(a, v1.w, o[7]);
            }
#pragma unroll
            for (int j = 0; j < 64; j++) {
                float vv = vs[c * 68 + j];
                float4 m0 = *(const float4*)&mwsT[j * 68 + x0];
                float4 m1 = *(const float4*)&mwsT[j * 68 + x0 + 4];
                g[0] = fmaf(vv, m0.x, g[0]); g[1] = fmaf(vv, m0.y, g[1]);
                g[2] = fmaf(vv, m0.z, g[2]); g[3] = fmaf(vv, m0.w, g[3]);
                g[4] = fmaf(vv, m1.x, g[4]); g[5] = fmaf(vv, m1.y, g[5]);
                g[6] = fmaf(vv, m1.z, g[6]); g[7] = fmaf(vv, m1.w, g[7]);
            }

            const int b = winId >> 10, rem = winId & 1023;
            const int h1 = rem >> 5, w1 = rem & 31;
            const int hh = x0 >> 3;
            const int h = h1 * 8 + hh;
            size_t outBase = (((size_t)b * C_IN + head * CH + c) * IMG + h) * IMG + w1 * 8;
#pragma unroll
            for (int xx = 0; xx < 8; xx++) {
                float x = g[xx];
                float ge = 0.5f * x * (1.0f + erff(x * 0.70710678118654752f));
                out[outBase + xx] = o[xx] * ge;
            }
        }
    }
}

// ---------------------------------------------------------------------------
extern "C" void kernel_launch(void* const* d_in, const int* in_sizes, int n_in,
                              void* d_out, int out_size)
{
    const float* x           = (const float*)d_in[0];
    const float* w_qkv       = (const float*)d_in[1];
    const float* w_dw        = (const float*)d_in[2];
    const float* temperature = (const float*)d_in[3];
    const float* mlp_w       = (const float*)d_in[4];
    const float* mlp_b       = (const float*)d_in[5];
    const float* proj_w      = (const float*)d_in[6];
    const float* proj_b      = (const float*)d_in[7];
    float* out = (float*)d_out;

    float *qkv1, *winb, *att;
    cudaGetSymbolAddress((void**)&qkv1, g_qkv1);
    cudaGetSymbolAddress((void**)&winb, g_win);
    cudaGetSymbolAddress((void**)&att, g_att);

    k_gemm_mma<<<dim3(HW / 128, C3 / 64, BATCH), 256>>>(w_qkv, x, qkv1, nullptr, C3);
    k_dwconv<<<dim3(IMG / 32, IMG / 8, BATCH * C3), dim3(32, 8)>>>(qkv1, w_dw, winb);
    k_attn<<<NWIN, 256>>>(winb, temperature, mlp_w, mlp_b, att);
    k_gemm_mma<<<dim3(HW / 128, C_IN / 64, BATCH), 256>>>(proj_w, att, out, proj_b, C_IN);
}

// round 7
// speedup vs baseline: 1.9950x; 1.4598x over previous
#include <cuda_runtime.h>
#include <cuda_bf16.h>
#include <math.h>
#include <stdint.h>

// ---------------- problem constants ----------------
#define BATCH 2
#define C_IN 192
#define C3 576
#define HW 65536
#define IMG 256
#define HEADS 6
#define CH 32
#define WS 8
#define NTOK 64
#define NWIN 2048

__device__ float g_qkv1[(size_t)BATCH * C3 * HW];
__device__ float g_win[(size_t)3 * NWIN * HEADS * CH * NTOK];
__device__ float g_att[(size_t)BATCH * C_IN * HW];

// ---------------------------------------------------------------------------
// bf16 helpers (pair-packed b32: low 16 = even-k, high 16 = odd-k)
// ---------------------------------------------------------------------------
__device__ __forceinline__ void split2(float e0, float e1, uint32_t& hp, uint32_t& lp)
{
    __nv_bfloat16 h0 = __float2bfloat16(e0);
    __nv_bfloat16 h1 = __float2bfloat16(e1);
    __nv_bfloat16 l0 = __float2bfloat16(e0 - __bfloat162float(h0));
    __nv_bfloat16 l1 = __float2bfloat16(e1 - __bfloat162float(h1));
    __nv_bfloat162 hh; hh.x = h0; hh.y = h1;
    __nv_bfloat162 ll; ll.x = l0; ll.y = l1;
    hp = *reinterpret_cast<uint32_t*>(&hh);
    lp = *reinterpret_cast<uint32_t*>(&ll);
}

__device__ __forceinline__ uint32_t pack_hi(float e0, float e1)
{
    __nv_bfloat162 hh; hh.x = __float2bfloat16(e0); hh.y = __float2bfloat16(e1);
    return *reinterpret_cast<uint32_t*>(&hh);
}

__device__ __forceinline__ void mma16816(float* d, const uint32_t* a, uint32_t b0, uint32_t b1)
{
    asm volatile(
        "mma.sync.aligned.m16n8k16.row.col.f32.bf16.bf16.f32 "
        "{%0,%1,%2,%3}, {%4,%5,%6,%7}, {%8,%9}, {%0,%1,%2,%3};"
        : "+f"(d[0]), "+f"(d[1]), "+f"(d[2]), "+f"(d[3])
        : "r"(a[0]), "r"(a[1]), "r"(a[2]), "r"(a[3]), "r"(b0), "r"(b1));
}

// ---------------------------------------------------------------------------
// K1/K4: GEMM Y[o,p] = sum_c W[o,c] * X[c,p] (+bias), K=192, bf16-split MMA.
// (unchanged from R6 — proven)
// ---------------------------------------------------------------------------
__global__ __launch_bounds__(256) void k_gemm_mma(
    const float* __restrict__ Wt, const float* __restrict__ Xall,
    float* __restrict__ Yall, const float* __restrict__ bias, int M)
{
    const float* X = Xall + (size_t)blockIdx.z * C_IN * HW;
    float* Y = Yall + (size_t)blockIdx.z * (size_t)M * HW;
    const int oTile = blockIdx.y * 64;
    const int pTile = blockIdx.x * 128;

    __shared__ uint32_t WsH[2][64][9], WsL[2][64][9];
    __shared__ uint32_t XsH[2][128][9], XsL[2][128][9];

    const int tid = threadIdx.x;
    const int lane = tid & 31;
    const int wid = tid >> 5;
    const int warpM = wid >> 2;
    const int warpN = wid & 3;
    const int gid = lane >> 2;
    const int tig = lane & 3;

    float acc[2][4][4];
#pragma unroll
    for (int im = 0; im < 2; im++)
#pragma unroll
        for (int jn = 0; jn < 4; jn++)
#pragma unroll
            for (int r = 0; r < 4; r++) acc[im][jn][r] = 0.f;

    const int wo = tid >> 2;
    const int wsub = tid & 3;
    const int xkp = tid >> 4;
    const int xp0 = (tid & 15) * 8;

    for (int k0 = 0; k0 < 192; k0 += 32) {
        {
            const float* wptr = &Wt[(size_t)(oTile + wo) * 192 + k0 + wsub * 8];
            float4 f0 = *(const float4*)wptr;
            float4 f1 = *(const float4*)(wptr + 4);
            float f[8] = {f0.x, f0.y, f0.z, f0.w, f1.x, f1.y, f1.z, f1.w};
#pragma unroll
            for (int j = 0; j < 4; j++) {
                uint32_t hp, lp;
                split2(f[2 * j], f[2 * j + 1], hp, lp);
                int kk2 = wsub * 4 + j;
                int ch = kk2 >> 3, cc = kk2 & 7;
                WsH[ch][wo][cc] = hp;
                WsL[ch][wo][cc] = lp;
            }
        }
        {
            const float* xr0 = &X[(size_t)(k0 + 2 * xkp) * HW + pTile + xp0];
            const float* xr1 = xr0 + HW;
            float4 a0 = *(const float4*)xr0;
            float4 a1 = *(const float4*)(xr0 + 4);
            float4 b0 = *(const float4*)xr1;
            float4 b1 = *(const float4*)(xr1 + 4);
            float fe[8] = {a0.x, a0.y, a0.z, a0.w, a1.x, a1.y, a1.z, a1.w};
            float fo[8] = {b0.x, b0.y, b0.z, b0.w, b1.x, b1.y, b1.z, b1.w};
            int ch = xkp >> 3, cc = xkp & 7;
#pragma unroll
            for (int n = 0; n < 8; n++) {
                uint32_t hp, lp;
                split2(fe[n], fo[n], hp, lp);
                XsH[ch][xp0 + n][cc] = hp;
                XsL[ch][xp0 + n][cc] = lp;
            }
        }
        __syncthreads();

#pragma unroll
        for (int ch = 0; ch < 2; ch++) {
            uint32_t Ah[2][4], Al[2][4];
#pragma unroll
            for (int im = 0; im < 2; im++) {
                int r0 = warpM * 32 + im * 16 + gid;
                Ah[im][0] = WsH[ch][r0][tig];
                Ah[im][1] = WsH[ch][r0 + 8][tig];
                Ah[im][2] = WsH[ch][r0][tig + 4];
                Ah[im][3] = WsH[ch][r0 + 8][tig + 4];
                Al[im][0] = WsL[ch][r0][tig];
                Al[im][1] = WsL[ch][r0 + 8][tig];
                Al[im][2] = WsL[ch][r0][tig + 4];
                Al[im][3] = WsL[ch][r0 + 8][tig + 4];
            }
#pragma unroll
            for (int jn = 0; jn < 4; jn++) {
                int col = warpN * 32 + jn * 8 + gid;
                uint32_t bh0 = XsH[ch][col][tig], bh1 = XsH[ch][col][tig + 4];
                uint32_t bl0 = XsL[ch][col][tig], bl1 = XsL[ch][col][tig + 4];
#pragma unroll
                for (int im = 0; im < 2; im++) {
                    mma16816(acc[im][jn], Al[im], bh0, bh1);
                    mma16816(acc[im][jn], Ah[im], bl0, bl1);
                    mma16816(acc[im][jn], Ah[im], bh0, bh1);
                }
            }
        }
        __syncthreads();
    }

#pragma unroll
    for (int im = 0; im < 2; im++) {
        int row = oTile + warpM * 32 + im * 16 + gid;
        float bs0 = bias ? bias[row] : 0.f;
        float bs1 = bias ? bias[row + 8] : 0.f;
#pragma unroll
        for (int jn = 0; jn < 4; jn++) {
            int col = pTile + warpN * 32 + jn * 8 + tig * 2;
            float2 r0 = make_float2(acc[im][jn][0] + bs0, acc[im][jn][1] + bs0);
            float2 r1 = make_float2(acc[im][jn][2] + bs1, acc[im][jn][3] + bs1);
            *(float2*)&Y[(size_t)row * HW + col] = r0;
            *(float2*)&Y[(size_t)(row + 8) * HW + col] = r1;
        }
    }
}

// ---------------------------------------------------------------------------
// K2: depthwise 3x3 (zero pad 1) + scatter into window layout
// ---------------------------------------------------------------------------
__global__ __launch_bounds__(256) void k_dwconv(
    const float* __restrict__ in, const float* __restrict__ wd,
    float* __restrict__ outWin)
{
    const int plane = blockIdx.z;
    const int b = plane / C3, ch3 = plane - b * C3;
    const int x0 = blockIdx.x * 32, y0 = blockIdx.y * 8;

    __shared__ float sm[10][34];
    const float* P = in + (size_t)plane * HW;
    const int tx = threadIdx.x, ty = threadIdx.y;
    const int lt = ty * 32 + tx;

    for (int e = lt; e < 340; e += 256) {
        int r = e / 34, cc = e - r * 34;
        int gy = y0 - 1 + r, gx = x0 - 1 + cc;
        float v = 0.f;
        if (gy >= 0 && gy < IMG && gx >= 0 && gx < IMG) v = P[gy * IMG + gx];
        sm[r][cc] = v;
    }
    __syncthreads();

    const float* wp = wd + ch3 * 9;
    float s = wp[0] * sm[ty + 0][tx + 0] + wp[1] * sm[ty + 0][tx + 1] + wp[2] * sm[ty + 0][tx + 2]
            + wp[3] * sm[ty + 1][tx + 0] + wp[4] * sm[ty + 1][tx + 1] + wp[5] * sm[ty + 1][tx + 2]
            + wp[6] * sm[ty + 2][tx + 0] + wp[7] * sm[ty + 2][tx + 1] + wp[8] * sm[ty + 2][tx + 2];

    const int h = y0 + ty, w = x0 + tx;
    const int z = ch3 / 192;
    const int head = (ch3 % 192) >> 5;
    const int c = ch3 & 31;
    const int win = b * 1024 + (h >> 3) * 32 + (w >> 3);
    const int tok = ((h & 7) << 3) + (w & 7);
    size_t dst = ((((size_t)z * NWIN + win) * HEADS + head) * CH + c) * NTOK + tok;
    outWin[dst] = s;
}

// ---------------------------------------------------------------------------
// K3 (MMA): one block per window, 256 threads = 8 warps, loops 6 heads.
// All three matmuls (QK^T, A·V, V·mlp_w^T) on tensor cores (bf16-split).
// smem layout (bytes):
//   mwh 0, mwl 8448          : mlp_w pairs over x, [y][xp] stride 33 (once/block)
//   qh 16896, kh 21120       : normalized q/k hi-only pairs [r][xp] stride 33
//   vph 25344, vpl 29568     : v pairs over x [c][xp] stride 33
//   vth 33792, vtl 38144     : v^T pairs over d [x][dp] stride 17
//   vs/As 42496 (aliased)    : fp32 staging 32x68 / attn logits 32x36
//   Ah 51200, Al 53376       : softmaxed attn pairs over d [c][dp] stride 17
//   mbs 55552
// ---------------------------------------------------------------------------
#define SMA_MWH 0
#define SMA_MWL 8448
#define SMA_QH 16896
#define SMA_KH 21120
#define SMA_VPH 25344
#define SMA_VPL 29568
#define SMA_VTH 33792
#define SMA_VTL 38144
#define SMA_VS  42496
#define SMA_AS  42496
#define SMA_AH  51200
#define SMA_AL  53376
#define SMA_MBS 55552
#define SMA_TOTAL 55808

__global__ __launch_bounds__(256) void k_attn(
    const float* __restrict__ winBuf, const float* __restrict__ temperature,
    const float* __restrict__ mlp_w, const float* __restrict__ mlp_b,
    float* __restrict__ out)
{
    extern __shared__ char smraw[];
    uint32_t* mwh = (uint32_t*)(smraw + SMA_MWH);
    uint32_t* mwl = (uint32_t*)(smraw + SMA_MWL);
    uint32_t* qh  = (uint32_t*)(smraw + SMA_QH);
    uint32_t* kh  = (uint32_t*)(smraw + SMA_KH);
    uint32_t* vph = (uint32_t*)(smraw + SMA_VPH);
    uint32_t* vpl = (uint32_t*)(smraw + SMA_VPL);
    uint32_t* vth = (uint32_t*)(smraw + SMA_VTH);
    uint32_t* vtl = (uint32_t*)(smraw + SMA_VTL);
    float*    vsf = (float*)(smraw + SMA_VS);
    float*    As  = (float*)(smraw + SMA_AS);
    uint32_t* Ahs = (uint32_t*)(smraw + SMA_AH);
    uint32_t* Als = (uint32_t*)(smraw + SMA_AL);
    float*    mbs = (float*)(smraw + SMA_MBS);

    const int winId = blockIdx.x;
    const int tid = threadIdx.x;
    const int lane = tid & 31;
    const int wid = tid >> 5;
    const int g = lane >> 2;
    const int t = lane & 3;
    const int mi = wid >> 2;        // 0..1 : M tile (rows mi*16)
    const int ni = wid & 3;         // 0..3

    const size_t zs = (size_t)NWIN * HEADS * CH * NTOK;

    // ---- mlp_w pack (once per block): y = tid>>2, 8 pairs ----
    {
        int y = tid >> 2, pp0 = (tid & 3) * 8;
        const float* p = mlp_w + y * 64 + pp0 * 2;
        float4 f0 = *(const float4*)p;
        float4 f1 = *(const float4*)(p + 4);
        float4 f2 = *(const float4*)(p + 8);
        float4 f3 = *(const float4*)(p + 12);
        float f[16] = {f0.x, f0.y, f0.z, f0.w, f1.x, f1.y, f1.z, f1.w,
                       f2.x, f2.y, f2.z, f2.w, f3.x, f3.y, f3.z, f3.w};
#pragma unroll
        for (int i = 0; i < 8; i++) {
            uint32_t hp, lp;
            split2(f[2 * i], f[2 * i + 1], hp, lp);
            mwh[y * 33 + pp0 + i] = hp;
            mwl[y * 33 + pp0 + i] = lp;
        }
    }
    if (tid < 64) mbs[tid] = mlp_b[tid];

    const int rr = tid >> 3;        // 0..31
    const int seg = tid & 7;        // 0..7

    const int bb = winId >> 10, rem = winId & 1023;
    const int h1 = rem >> 5, w1 = rem & 31;

    for (int head = 0; head < HEADS; head++) {
        const size_t base = (size_t)(winId * HEADS + head) * (CH * NTOK);
        __syncthreads();   // (a) protect smem reuse across heads

        // ---- q: load, l2norm, hi-pack ----
        {
            const float* p = winBuf + base + rr * 64 + seg * 8;
            float4 a = *(const float4*)p;
            float4 b = *(const float4*)(p + 4);
            float f[8] = {a.x, a.y, a.z, a.w, b.x, b.y, b.z, b.w};
            float ss = 0.f;
#pragma unroll
            for (int i = 0; i < 8; i++) ss += f[i] * f[i];
            ss += __shfl_xor_sync(0xffffffffu, ss, 1);
            ss += __shfl_xor_sync(0xffffffffu, ss, 2);
            ss += __shfl_xor_sync(0xffffffffu, ss, 4);
            float inv = 1.0f / fmaxf(sqrtf(ss), 1e-12f);
#pragma unroll
            for (int i = 0; i < 4; i++)
                qh[rr * 33 + seg * 4 + i] = pack_hi(f[2 * i] * inv, f[2 * i + 1] * inv);
        }
        // ---- k: load, l2norm, hi-pack ----
        {
            const float* p = winBuf + zs + base + rr * 64 + seg * 8;
            float4 a = *(const float4*)p;
            float4 b = *(const float4*)(p + 4);
            float f[8] = {a.x, a.y, a.z, a.w, b.x, b.y, b.z, b.w};
            float ss = 0.f;
#pragma unroll
            for (int i = 0; i < 8; i++) ss += f[i] * f[i];
            ss += __shfl_xor_sync(0xffffffffu, ss, 1);
            ss += __shfl_xor_sync(0xffffffffu, ss, 2);
            ss += __shfl_xor_sync(0xffffffffu, ss, 4);
            float inv = 1.0f / fmaxf(sqrtf(ss), 1e-12f);
#pragma unroll
            for (int i = 0; i < 4; i++)
                kh[rr * 33 + seg * 4 + i] = pack_hi(f[2 * i] * inv, f[2 * i + 1] * inv);
        }
        // ---- v: load, split-pack over x, and fp32 stage ----
        {
            const float* p = winBuf + 2 * zs + base + rr * 64 + seg * 8;
            float4 a = *(const float4*)p;
            float4 b = *(const float4*)(p + 4);
            float f[8] = {a.x, a.y, a.z, a.w, b.x, b.y, b.z, b.w};
#pragma unroll
            for (int i = 0; i < 4; i++) {
                uint32_t hp, lp;
                split2(f[2 * i], f[2 * i + 1], hp, lp);
                vph[rr * 33 + seg * 4 + i] = hp;
                vpl[rr * 33 + seg * 4 + i] = lp;
            }
            *(float4*)&vsf[rr * 68 + seg * 8] = a;
            *(float4*)&vsf[rr * 68 + seg * 8 + 4] = b;
        }
        __syncthreads();   // (b) vs staged

        // ---- build v^T pairs over d: x = tid>>2, dp = (tid&3) + 4i ----
        {
            int x = tid >> 2;
            int dpb = tid & 3;
#pragma unroll
            for (int i = 0; i < 4; i++) {
                int dp = dpb + 4 * i;
                float e0 = vsf[(2 * dp) * 68 + x];
                float e1 = vsf[(2 * dp + 1) * 68 + x];
                uint32_t hp, lp;
                split2(e0, e1, hp, lp);
                vth[x * 17 + dp] = hp;
                vtl[x * 17 + dp] = lp;
            }
        }
        __syncthreads();   // (c) packs ready (vs now dead -> As usable)

        // ---- QK^T (hi-only): warp tile m16n8 at (mi*16, ni*8), K=64 ----
        {
            float cacc[4] = {0.f, 0.f, 0.f, 0.f};
#pragma unroll
            for (int c = 0; c < 4; c++) {
                int p0 = c * 8 + t, p1 = p0 + 4;
                uint32_t A[4];
                A[0] = qh[(mi * 16 + g) * 33 + p0];
                A[1] = qh[(mi * 16 + g + 8) * 33 + p0];
                A[2] = qh[(mi * 16 + g) * 33 + p1];
                A[3] = qh[(mi * 16 + g + 8) * 33 + p1];
                uint32_t b0 = kh[(ni * 8 + g) * 33 + p0];
                uint32_t b1 = kh[(ni * 8 + g) * 33 + p1];
                mma16816(cacc, A, b0, b1);
            }
            const float temp = temperature[head];
            As[(mi * 16 + g) * 36 + ni * 8 + 2 * t] = cacc[0] * temp;
            As[(mi * 16 + g) * 36 + ni * 8 + 2 * t + 1] = cacc[1] * temp;
            As[(mi * 16 + g + 8) * 36 + ni * 8 + 2 * t] = cacc[2] * temp;
            As[(mi * 16 + g + 8) * 36 + ni * 8 + 2 * t + 1] = cacc[3] * temp;
        }
        __syncthreads();   // (d)

        // ---- softmax rows of As; emit split pairs Ah/Al ----
        {
            int r = tid >> 3, j0 = (tid & 7) * 4;
            float4 v4 = *(const float4*)&As[r * 36 + j0];
            float v[4] = {v4.x, v4.y, v4.z, v4.w};
            float m = fmaxf(fmaxf(v[0], v[1]), fmaxf(v[2], v[3]));
            m = fmaxf(m, __shfl_xor_sync(0xffffffffu, m, 1));
            m = fmaxf(m, __shfl_xor_sync(0xffffffffu, m, 2));
            m = fmaxf(m, __shfl_xor_sync(0xffffffffu, m, 4));
            float s = 0.f;
#pragma unroll
            for (int i = 0; i < 4; i++) { v[i] = __expf(v[i] - m); s += v[i]; }
            s += __shfl_xor_sync(0xffffffffu, s, 1);
            s += __shfl_xor_sync(0xffffffffu, s, 2);
            s += __shfl_xor_sync(0xffffffffu, s, 4);
            float inv = 1.0f / s;
            int jp = (tid & 7) * 2;
            uint32_t hp, lp;
            split2(v[0] * inv, v[1] * inv, hp, lp);
            Ahs[r * 17 + jp] = hp; Als[r * 17 + jp] = lp;
            split2(v[2] * inv, v[3] * inv, hp, lp);
            Ahs[r * 17 + jp + 1] = hp; Als[r * 17 + jp + 1] = lp;
        }
        __syncthreads();   // (e)

        // ---- A·V and V·mlp_w^T, same tiling; fused epilogue ----
        {
            float oa[2][4], ga[2][4];
#pragma unroll
            for (int nt = 0; nt < 2; nt++)
#pragma unroll
                for (int r = 0; r < 4; r++) { oa[nt][r] = 0.f; ga[nt][r] = 0.f; }

            // A·V : K=32 (2 chunks)
#pragma unroll
            for (int c = 0; c < 2; c++) {
                int p0 = c * 8 + t, p1 = p0 + 4;
                uint32_t Ahf[4], Alf[4];
                Ahf[0] = Ahs[(mi * 16 + g) * 17 + p0];
                Ahf[1] = Ahs[(mi * 16 + g + 8) * 17 + p0];
                Ahf[2] = Ahs[(mi * 16 + g) * 17 + p1];
                Ahf[3] = Ahs[(mi * 16 + g + 8) * 17 + p1];
                Alf[0] = Als[(mi * 16 + g) * 17 + p0];
                Alf[1] = Als[(mi * 16 + g + 8) * 17 + p0];
                Alf[2] = Als[(mi * 16 + g) * 17 + p1];
                Alf[3] = Als[(mi * 16 + g + 8) * 17 + p1];
#pragma unroll
                for (int nt = 0; nt < 2; nt++) {
                    int n = (ni * 2 + nt) * 8 + g;
                    uint32_t bh0 = vth[n * 17 + p0], bh1 = vth[n * 17 + p1];
                    uint32_t bl0 = vtl[n * 17 + p0], bl1 = vtl[n * 17 + p1];
                    mma16816(oa[nt], Ahf, bl0, bl1);
                    mma16816(oa[nt], Alf, bh0, bh1);
                    mma16816(oa[nt], Ahf, bh0, bh1);
                }
            }
            // gate: V·mlp_w^T : K=64 (4 chunks)
#pragma unroll
            for (int c = 0; c < 4; c++) {
                int p0 = c * 8 + t, p1 = p0 + 4;
                uint32_t Vh[4], Vl[4];
                Vh[0] = vph[(mi * 16 + g) * 33 + p0];
                Vh[1] = vph[(mi * 16 + g + 8) * 33 + p0];
                Vh[2] = vph[(mi * 16 + g) * 33 + p1];
                Vh[3] = vph[(mi * 16 + g + 8) * 33 + p1];
                Vl[0] = vpl[(mi * 16 + g) * 33 + p0];
                Vl[1] = vpl[(mi * 16 + g + 8) * 33 + p0];
                Vl[2] = vpl[(mi * 16 + g) * 33 + p1];
                Vl[3] = vpl[(mi * 16 + g + 8) * 33 + p1];
#pragma unroll
                for (int nt = 0; nt < 2; nt++) {
                    int n = (ni * 2 + nt) * 8 + g;
                    uint32_t bh0 = mwh[n * 33 + p0], bh1 = mwh[n * 33 + p1];
                    uint32_t bl0 = mwl[n * 33 + p0], bl1 = mwl[n * 33 + p1];
                    mma16816(ga[nt], Vh, bl0, bl1);
                    mma16816(ga[nt], Vl, bh0, bh1);
                    mma16816(ga[nt], Vh, bh0, bh1);
                }
            }
            // epilogue: out[c][x] = O[c][x] * gelu(gate[c][x] + b[x])
#pragma unroll
            for (int nt = 0; nt < 2; nt++) {
                int ntok = ni * 2 + nt;               // token row (x>>3)
                float b0 = mbs[ntok * 8 + 2 * t];
                float b1 = mbs[ntok * 8 + 2 * t + 1];
#pragma unroll
                for (int half = 0; half < 2; half++) {
                    int row = mi * 16 + g + half * 8;  // channel c
                    float o0 = oa[nt][half * 2], o1 = oa[nt][half * 2 + 1];
                    float x0 = ga[nt][half * 2] + b0;
                    float x1 = ga[nt][half * 2 + 1] + b1;
                    float ge0 = 0.5f * x0 * (1.0f + erff(x0 * 0.70710678118654752f));
                    float ge1 = 0.5f * x1 * (1.0f + erff(x1 * 0.70710678118654752f));
                    size_t addr = ((((size_t)bb * C_IN + head * CH + row) * IMG
                                    + h1 * 8 + ntok) * IMG) + w1 * 8 + 2 * t;
                    *(float2*)&out[addr] = make_float2(o0 * ge0, o1 * ge1);
                }
            }
        }
    }
}

// ---------------------------------------------------------------------------
extern "C" void kernel_launch(void* const* d_in, const int* in_sizes, int n_in,
                              void* d_out, int out_size)
{
    const float* x           = (const float*)d_in[0];
    const float* w_qkv       = (const float*)d_in[1];
    const float* w_dw        = (const float*)d_in[2];
    const float* temperature = (const float*)d_in[3];
    const float* mlp_w       = (const float*)d_in[4];
    const float* mlp_b       = (const float*)d_in[5];
    const float* proj_w      = (const float*)d_in[6];
    const float* proj_b      = (const float*)d_in[7];
    float* out = (float*)d_out;

    float *qkv1, *winb, *att;
    cudaGetSymbolAddress((void**)&qkv1, g_qkv1);
    cudaGetSymbolAddress((void**)&winb, g_win);
    cudaGetSymbolAddress((void**)&att, g_att);

    cudaFuncSetAttribute(k_attn, cudaFuncAttributeMaxDynamicSharedMemorySize, SMA_TOTAL);

    k_gemm_mma<<<dim3(HW / 128, C3 / 64, BATCH), 256>>>(w_qkv, x, qkv1, nullptr, C3);
    k_dwconv<<<dim3(IMG / 32, IMG / 8, BATCH * C3), dim3(32, 8)>>>(qkv1, w_dw, winb);
    k_attn<<<NWIN, 256, SMA_TOTAL>>>(winb, temperature, mlp_w, mlp_b, att);
    k_gemm_mma<<<dim3(HW / 128, C_IN / 64, BATCH), 256>>>(proj_w, att, out, proj_b, C_IN);
}

// round 9
// speedup vs baseline: 2.1412x; 1.0732x over previous
#include <cuda_runtime.h>
#include <cuda_bf16.h>
#include <math.h>
#include <stdint.h>

// ---------------- problem constants ----------------
#define BATCH 2
#define C_IN 192
#define C3 576
#define HW 65536
#define IMG 256
#define HEADS 6
#define CH 32
#define WS 8
#define NTOK 64
#define NWIN 2048

__device__ float g_qkv1[(size_t)BATCH * C3 * HW];
__device__ float g_win[(size_t)3 * NWIN * HEADS * CH * NTOK];
__device__ float g_att[(size_t)BATCH * C_IN * HW];

// ---------------------------------------------------------------------------
// bf16 helpers (pair-packed b32: low 16 = even-k, high 16 = odd-k)
// ---------------------------------------------------------------------------
__device__ __forceinline__ void split2(float e0, float e1, uint32_t& hp, uint32_t& lp)
{
    __nv_bfloat16 h0 = __float2bfloat16(e0);
    __nv_bfloat16 h1 = __float2bfloat16(e1);
    __nv_bfloat16 l0 = __float2bfloat16(e0 - __bfloat162float(h0));
    __nv_bfloat16 l1 = __float2bfloat16(e1 - __bfloat162float(h1));
    __nv_bfloat162 hh; hh.x = h0; hh.y = h1;
    __nv_bfloat162 ll; ll.x = l0; ll.y = l1;
    hp = *reinterpret_cast<uint32_t*>(&hh);
    lp = *reinterpret_cast<uint32_t*>(&ll);
}

__device__ __forceinline__ uint32_t pack_hi(float e0, float e1)
{
    __nv_bfloat162 hh; hh.x = __float2bfloat16(e0); hh.y = __float2bfloat16(e1);
    return *reinterpret_cast<uint32_t*>(&hh);
}

__device__ __forceinline__ void mma16816(float* d, const uint32_t* a, uint32_t b0, uint32_t b1)
{
    asm volatile(
        "mma.sync.aligned.m16n8k16.row.col.f32.bf16.bf16.f32 "
        "{%0,%1,%2,%3}, {%4,%5,%6,%7}, {%8,%9}, {%0,%1,%2,%3};"
        : "+f"(d[0]), "+f"(d[1]), "+f"(d[2]), "+f"(d[3])
        : "r"(a[0]), "r"(a[1]), "r"(a[2]), "r"(a[3]), "r"(b0), "r"(b1));
}

// ---------------------------------------------------------------------------
// K1/K4: GEMM Y[o,p] = sum_c W[o,c] * X[c,p] (+bias), K=192, bf16-split MMA.
// CTA tile 64(M) x 256(N) x 32(K); 8 warps in 2x4; warp tile 32x64.
// X pack stores are conflict-free: each lane owns p == lane (mod 32),
// smem stride 9 (coprime with 32 banks).
// ---------------------------------------------------------------------------
__global__ __launch_bounds__(256) void k_gemm_mma(
    const float* __restrict__ Wt, const float* __restrict__ Xall,
    float* __restrict__ Yall, const float* __restrict__ bias, int M)
{
    const float* X = Xall + (size_t)blockIdx.z * C_IN * HW;
    float* Y = Yall + (size_t)blockIdx.z * (size_t)M * HW;
    const int oTile = blockIdx.y * 64;
    const int pTile = blockIdx.x * 256;

    __shared__ uint32_t WsH[2][64][9], WsL[2][64][9];
    __shared__ uint32_t XsH[2][256][9], XsL[2][256][9];

    const int tid = threadIdx.x;
    const int lane = tid & 31;
    const int wid = tid >> 5;
    const int warpM = wid >> 2;     // 0..1 -> rows warpM*32
    const int warpN = wid & 3;      // 0..3 -> cols warpN*64
    const int g = lane >> 2;        // 0..7
    const int t = lane & 3;         // 0..3

    float acc[2][8][4];
#pragma unroll
    for (int im = 0; im < 2; im++)
#pragma unroll
        for (int jn = 0; jn < 8; jn++)
#pragma unroll
            for (int r = 0; r < 4; r++) acc[im][jn][r] = 0.f;

    const int wo = tid >> 2;            // 0..63 : W row in tile
    const int wsub = tid & 3;           // 0..3  : 8-k chunk

    for (int k0 = 0; k0 < 192; k0 += 32) {
        // ---- W tile (64 x 32), float4 loads, pair-packed stores ----
        {
            const float* wptr = &Wt[(size_t)(oTile + wo) * 192 + k0 + wsub * 8];
            float4 f0 = *(const float4*)wptr;
            float4 f1 = *(const float4*)(wptr + 4);
            float f[8] = {f0.x, f0.y, f0.z, f0.w, f1.x, f1.y, f1.z, f1.w};
#pragma unroll
            for (int j = 0; j < 4; j++) {
                uint32_t hp, lp;
                split2(f[2 * j], f[2 * j + 1], hp, lp);
                int kk2 = wsub * 4 + j;
                int ch = kk2 >> 3, cc = kk2 & 7;
                WsH[ch][wo][cc] = hp;
                WsL[ch][wo][cc] = lp;
            }
        }
        // ---- X tile (32 x 256): conflict-free pack stores ----
        {
#pragma unroll
            for (int it = 0; it < 2; it++) {
                int kp = (tid >> 5) + it * 8;       // 0..15
                int ch = kp >> 3, cc = kp & 7;
                const float* r0 = X + (size_t)(k0 + 2 * kp) * HW + pTile + lane;
#pragma unroll
                for (int pm = 0; pm < 8; pm++) {
                    float f0 = r0[pm * 32];
                    float f1 = r0[pm * 32 + HW];
                    uint32_t hp, lp;
                    split2(f0, f1, hp, lp);
                    XsH[ch][lane + 32 * pm][cc] = hp;
                    XsL[ch][lane + 32 * pm][cc] = lp;
                }
            }
        }
        __syncthreads();

#pragma unroll
        for (int ch = 0; ch < 2; ch++) {
            uint32_t Ah[2][4], Al[2][4];
#pragma unroll
            for (int im = 0; im < 2; im++) {
                int r0 = warpM * 32 + im * 16 + g;
                Ah[im][0] = WsH[ch][r0][t];
                Ah[im][1] = WsH[ch][r0 + 8][t];
                Ah[im][2] = WsH[ch][r0][t + 4];
                Ah[im][3] = WsH[ch][r0 + 8][t + 4];
                Al[im][0] = WsL[ch][r0][t];
                Al[im][1] = WsL[ch][r0 + 8][t];
                Al[im][2] = WsL[ch][r0][t + 4];
                Al[im][3] = WsL[ch][r0 + 8][t + 4];
            }
#pragma unroll
            for (int jn = 0; jn < 8; jn++) {
                int col = warpN * 64 + jn * 8 + g;
                uint32_t bh0 = XsH[ch][col][t], bh1 = XsH[ch][col][t + 4];
                uint32_t bl0 = XsL[ch][col][t], bl1 = XsL[ch][col][t + 4];
#pragma unroll
                for (int im = 0; im < 2; im++) {
                    mma16816(acc[im][jn], Al[im], bh0, bh1);
                    mma16816(acc[im][jn], Ah[im], bl0, bl1);
                    mma16816(acc[im][jn], Ah[im], bh0, bh1);
                }
            }
        }
        __syncthreads();
    }

    // ---- epilogue ----
#pragma unroll
    for (int im = 0; im < 2; im++) {
        int row = oTile + warpM * 32 + im * 16 + g;
        float bs0 = bias ? bias[row] : 0.f;
        float bs1 = bias ? bias[row + 8] : 0.f;
#pragma unroll
        for (int jn = 0; jn < 8; jn++) {
            int col = pTile + warpN * 64 + jn * 8 + t * 2;
            float2 r0 = make_float2(acc[im][jn][0] + bs0, acc[im][jn][1] + bs0);
            float2 r1 = make_float2(acc[im][jn][2] + bs1, acc[im][jn][3] + bs1);
            *(float2*)&Y[(size_t)row * HW + col] = r0;
            *(float2*)&Y[(size_t)(row + 8) * HW + col] = r1;
        }
    }
}

// ---------------------------------------------------------------------------
// K2: depthwise 3x3 (zero pad 1) + scatter into window layout
// ---------------------------------------------------------------------------
__global__ __launch_bounds__(256) void k_dwconv(
    const float* __restrict__ in, const float* __restrict__ wd,
    float* __restrict__ outWin)
{
    const int plane = blockIdx.z;
    const int b = plane / C3, ch3 = plane - b * C3;
    const int x0 = blockIdx.x * 32, y0 = blockIdx.y * 8;

    __shared__ float sm[10][34];
    const float* P = in + (size_t)plane * HW;
    const int tx = threadIdx.x, ty = threadIdx.y;
    const int lt = ty * 32 + tx;

    for (int e = lt; e < 340; e += 256) {
        int r = e / 34, cc = e - r * 34;
        int gy = y0 - 1 + r, gx = x0 - 1 + cc;
        float v = 0.f;
        if (gy >= 0 && gy < IMG && gx >= 0 && gx < IMG) v = P[gy * IMG + gx];
        sm[r][cc] = v;
    }
    __syncthreads();

    const float* wp = wd + ch3 * 9;
    float s = wp[0] * sm[ty + 0][tx + 0] + wp[1] * sm[ty + 0][tx + 1] + wp[2] * sm[ty + 0][tx + 2]
            + wp[3] * sm[ty + 1][tx + 0] + wp[4] * sm[ty + 1][tx + 1] + wp[5] * sm[ty + 1][tx + 2]
            + wp[6] * sm[ty + 2][tx + 0] + wp[7] * sm[ty + 2][tx + 1] + wp[8] * sm[ty + 2][tx + 2];

    const int h = y0 + ty, w = x0 + tx;
    const int z = ch3 / 192;
    const int head = (ch3 % 192) >> 5;
    const int c = ch3 & 31;
    const int win = b * 1024 + (h >> 3) * 32 + (w >> 3);
    const int tok = ((h & 7) << 3) + (w & 7);
    size_t dst = ((((size_t)z * NWIN + win) * HEADS + head) * CH + c) * NTOK + tok;
    outWin[dst] = s;
}

// ---------------------------------------------------------------------------
// K3 (register MMA): one block per window, 8 warps, loops 6 heads. (R7, proven)
// ---------------------------------------------------------------------------
#define SMA_MWH 0
#define SMA_MWL 8448
#define SMA_QH 16896
#define SMA_KH 21120
#define SMA_VPH 25344
#define SMA_VPL 29568
#define SMA_VTH 33792
#define SMA_VTL 38144
#define SMA_VS  42496
#define SMA_AS  42496
#define SMA_AH  51200
#define SMA_AL  53376
#define SMA_MBS 55552
#define SMA_TOTAL 55808

__global__ __launch_bounds__(256) void k_attn(
    const float* __restrict__ winBuf, const float* __restrict__ temperature,
    const float* __restrict__ mlp_w, const float* __restrict__ mlp_b,
    float* __restrict__ out)
{
    extern __shared__ char smraw[];
    uint32_t* mwh = (uint32_t*)(smraw + SMA_MWH);
    uint32_t* mwl = (uint32_t*)(smraw + SMA_MWL);
    uint32_t* qh  = (uint32_t*)(smraw + SMA_QH);
    uint32_t* kh  = (uint32_t*)(smraw + SMA_KH);
    uint32_t* vph = (uint32_t*)(smraw + SMA_VPH);
    uint32_t* vpl = (uint32_t*)(smraw + SMA_VPL);
    uint32_t* vth = (uint32_t*)(smraw + SMA_VTH);
    uint32_t* vtl = (uint32_t*)(smraw + SMA_VTL);
    float*    vsf = (float*)(smraw + SMA_VS);
    float*    As  = (float*)(smraw + SMA_AS);
    uint32_t* Ahs = (uint32_t*)(smraw + SMA_AH);
    uint32_t* Als = (uint32_t*)(smraw + SMA_AL);
    float*    mbs = (float*)(smraw + SMA_MBS);

    const int winId = blockIdx.x;
    const int tid = threadIdx.x;
    const int lane = tid & 31;
    const int wid = tid >> 5;
    const int g = lane >> 2;
    const int t = lane & 3;
    const int mi = wid >> 2;
    const int ni = wid & 3;

    const size_t zs = (size_t)NWIN * HEADS * CH * NTOK;

    {
        int y = tid >> 2, pp0 = (tid & 3) * 8;
        const float* p = mlp_w + y * 64 + pp0 * 2;
        float4 f0 = *(const float4*)p;
        float4 f1 = *(const float4*)(p + 4);
        float4 f2 = *(const float4*)(p + 8);
        float4 f3 = *(const float4*)(p + 12);
        float f[16] = {f0.x, f0.y, f0.z, f0.w, f1.x, f1.y, f1.z, f1.w,
                       f2.x, f2.y, f2.z, f2.w, f3.x, f3.y, f3.z, f3.w};
#pragma unroll
        for (int i = 0; i < 8; i++) {
            uint32_t hp, lp;
            split2(f[2 * i], f[2 * i + 1], hp, lp);
            mwh[y * 33 + pp0 + i] = hp;
            mwl[y * 33 + pp0 + i] = lp;
        }
    }
    if (tid < 64) mbs[tid] = mlp_b[tid];

    const int rr = tid >> 3;
    const int seg = tid & 7;

    const int bb = winId >> 10, rem = winId & 1023;
    const int h1 = rem >> 5, w1 = rem & 31;

    for (int head = 0; head < HEADS; head++) {
        const size_t base = (size_t)(winId * HEADS + head) * (CH * NTOK);
        __syncthreads();

        {
            const float* p = winBuf + base + rr * 64 + seg * 8;
            float4 a = *(const float4*)p;
            float4 b = *(const float4*)(p + 4);
            float f[8] = {a.x, a.y, a.z, a.w, b.x, b.y, b.z, b.w};
            float ss = 0.f;
#pragma unroll
            for (int i = 0; i < 8; i++) ss += f[i] * f[i];
            ss += __shfl_xor_sync(0xffffffffu, ss, 1);
            ss += __shfl_xor_sync(0xffffffffu, ss, 2);
            ss += __shfl_xor_sync(0xffffffffu, ss, 4);
            float inv = 1.0f / fmaxf(sqrtf(ss), 1e-12f);
#pragma unroll
            for (int i = 0; i < 4; i++)
                qh[rr * 33 + seg * 4 + i] = pack_hi(f[2 * i] * inv, f[2 * i + 1] * inv);
        }
        {
            const float* p = winBuf + zs + base + rr * 64 + seg * 8;
            float4 a = *(const float4*)p;
            float4 b = *(const float4*)(p + 4);
            float f[8] = {a.x, a.y, a.z, a.w, b.x, b.y, b.z, b.w};
            float ss = 0.f;
#pragma unroll
            for (int i = 0; i < 8; i++) ss += f[i] * f[i];
            ss += __shfl_xor_sync(0xffffffffu, ss, 1);
            ss += __shfl_xor_sync(0xffffffffu, ss, 2);
            ss += __shfl_xor_sync(0xffffffffu, ss, 4);
            float inv = 1.0f / fmaxf(sqrtf(ss), 1e-12f);
#pragma unroll
            for (int i = 0; i < 4; i++)
                kh[rr * 33 + seg * 4 + i] = pack_hi(f[2 * i] * inv, f[2 * i + 1] * inv);
        }
        {
            const float* p = winBuf + 2 * zs + base + rr * 64 + seg * 8;
            float4 a = *(const float4*)p;
            float4 b = *(const float4*)(p + 4);
            float f[8] = {a.x, a.y, a.z, a.w, b.x, b.y, b.z, b.w};
#pragma unroll
            for (int i = 0; i < 4; i++) {
                uint32_t hp, lp;
                split2(f[2 * i], f[2 * i + 1], hp, lp);
                vph[rr * 33 + seg * 4 + i] = hp;
                vpl[rr * 33 + seg * 4 + i] = lp;
            }
            *(float4*)&vsf[rr * 68 + seg * 8] = a;
            *(float4*)&vsf[rr * 68 + seg * 8 + 4] = b;
        }
        __syncthreads();

        {
            int x = tid >> 2;
            int dpb = tid & 3;
#pragma unroll
            for (int i = 0; i < 4; i++) {
                int dp = dpb + 4 * i;
                float e0 = vsf[(2 * dp) * 68 + x];
                float e1 = vsf[(2 * dp + 1) * 68 + x];
                uint32_t hp, lp;
                split2(e0, e1, hp, lp);
                vth[x * 17 + dp] = hp;
                vtl[x * 17 + dp] = lp;
            }
        }
        __syncthreads();

        {
            float cacc[4] = {0.f, 0.f, 0.f, 0.f};
#pragma unroll
            for (int c = 0; c < 4; c++) {
                int p0 = c * 8 + t, p1 = p0 + 4;
                uint32_t A[4];
                A[0] = qh[(mi * 16 + g) * 33 + p0];
                A[1] = qh[(mi * 16 + g + 8) * 33 + p0];
                A[2] = qh[(mi * 16 + g) * 33 + p1];
                A[3] = qh[(mi * 16 + g + 8) * 33 + p1];
                uint32_t b0 = kh[(ni * 8 + g) * 33 + p0];
                uint32_t b1 = kh[(ni * 8 + g) * 33 + p1];
                mma16816(cacc, A, b0, b1);
            }
            const float temp = temperature[head];
            As[(mi * 16 + g) * 36 + ni * 8 + 2 * t] = cacc[0] * temp;
            As[(mi * 16 + g) * 36 + ni * 8 + 2 * t + 1] = cacc[1] * temp;
            As[(mi * 16 + g + 8) * 36 + ni * 8 + 2 * t] = cacc[2] * temp;
            As[(mi * 16 + g + 8) * 36 + ni * 8 + 2 * t + 1] = cacc[3] * temp;
        }
        __syncthreads();

        {
            int r = tid >> 3, j0 = (tid & 7) * 4;
            float4 v4 = *(const float4*)&As[r * 36 + j0];
            float v[4] = {v4.x, v4.y, v4.z, v4.w};
            float m = fmaxf(fmaxf(v[0], v[1]), fmaxf(v[2], v[3]));
            m = fmaxf(m, __shfl_xor_sync(0xffffffffu, m, 1));
            m = fmaxf(m, __shfl_xor_sync(0xffffffffu, m, 2));
            m = fmaxf(m, __shfl_xor_sync(0xffffffffu, m, 4));
            float s = 0.f;
#pragma unroll
            for (int i = 0; i < 4; i++) { v[i] = __expf(v[i] - m); s += v[i]; }
            s += __shfl_xor_sync(0xffffffffu, s, 1);
            s += __shfl_xor_sync(0xffffffffu, s, 2);
            s += __shfl_xor_sync(0xffffffffu, s, 4);
            float inv = 1.0f / s;
            int jp = (tid & 7) * 2;
            uint32_t hp, lp;
            split2(v[0] * inv, v[1] * inv, hp, lp);
            Ahs[r * 17 + jp] = hp; Als[r * 17 + jp] = lp;
            split2(v[2] * inv, v[3] * inv, hp, lp);
            Ahs[r * 17 + jp + 1] = hp; Als[r * 17 + jp + 1] = lp;
        }
        __syncthreads();

        {
            float oa[2][4], ga[2][4];
#pragma unroll
            for (int nt = 0; nt < 2; nt++)
#pragma unroll
                for (int r = 0; r < 4; r++) { oa[nt][r] = 0.f; ga[nt][r] = 0.f; }

#pragma unroll
            for (int c = 0; c < 2; c++) {
                int p0 = c * 8 + t, p1 = p0 + 4;
                uint32_t Ahf[4], Alf[4];
                Ahf[0] = Ahs[(mi * 16 + g) * 17 + p0];
                Ahf[1] = Ahs[(mi * 16 + g + 8) * 17 + p0];
                Ahf[2] = Ahs[(mi * 16 + g) * 17 + p1];
                Ahf[3] = Ahs[(mi * 16 + g + 8) * 17 + p1];
                Alf[0] = Als[(mi * 16 + g) * 17 + p0];
                Alf[1] = Als[(mi * 16 + g + 8) * 17 + p0];
                Alf[2] = Als[(mi * 16 + g) * 17 + p1];
                Alf[3] = Als[(mi * 16 + g + 8) * 17 + p1];
#pragma unroll
                for (int nt = 0; nt < 2; nt++) {
                    int n = (ni * 2 + nt) * 8 + g;
                    uint32_t bh0 = vth[n * 17 + p0], bh1 = vth[n * 17 + p1];
                    uint32_t bl0 = vtl[n * 17 + p0], bl1 = vtl[n * 17 + p1];
                    mma16816(oa[nt], Ahf, bl0, bl1);
                    mma16816(oa[nt], Alf, bh0, bh1);
                    mma16816(oa[nt], Ahf, bh0, bh1);
                }
            }
#pragma unroll
            for (int c = 0; c < 4; c++) {
                int p0 = c * 8 + t, p1 = p0 + 4;
                uint32_t Vh[4], Vl[4];
                Vh[0] = vph[(mi * 16 + g) * 33 + p0];
                Vh[1] = vph[(mi * 16 + g + 8) * 33 + p0];
                Vh[2] = vph[(mi * 16 + g) * 33 + p1];
                Vh[3] = vph[(mi * 16 + g + 8) * 33 + p1];
                Vl[0] = vpl[(mi * 16 + g) * 33 + p0];
                Vl[1] = vpl[(mi * 16 + g + 8) * 33 + p0];
                Vl[2] = vpl[(mi * 16 + g) * 33 + p1];
                Vl[3] = vpl[(mi * 16 + g + 8) * 33 + p1];
#pragma unroll
                for (int nt = 0; nt < 2; nt++) {
                    int n = (ni * 2 + nt) * 8 + g;
                    uint32_t bh0 = mwh[n * 33 + p0], bh1 = mwh[n * 33 + p1];
                    uint32_t bl0 = mwl[n * 33 + p0], bl1 = mwl[n * 33 + p1];
                    mma16816(ga[nt], Vh, bl0, bl1);
                    mma16816(ga[nt], Vl, bh0, bh1);
                    mma16816(ga[nt], Vh, bh0, bh1);
                }
            }
#pragma unroll
            for (int nt = 0; nt < 2; nt++) {
                int ntok = ni * 2 + nt;
                float b0 = mbs[ntok * 8 + 2 * t];
                float b1 = mbs[ntok * 8 + 2 * t + 1];
#pragma unroll
                for (int half = 0; half < 2; half++) {
                    int row = mi * 16 + g + half * 8;
                    float o0 = oa[nt][half * 2], o1 = oa[nt][half * 2 + 1];
                    float x0 = ga[nt][half * 2] + b0;
                    float x1 = ga[nt][half * 2 + 1] + b1;
                    float ge0 = 0.5f * x0 * (1.0f + erff(x0 * 0.70710678118654752f));
                    float ge1 = 0.5f * x1 * (1.0f + erff(x1 * 0.70710678118654752f));
                    size_t addr = ((((size_t)bb * C_IN + head * CH + row) * IMG
                                    + h1 * 8 + ntok) * IMG) + w1 * 8 + 2 * t;
                    *(float2*)&out[addr] = make_float2(o0 * ge0, o1 * ge1);
                }
            }
        }
    }
}

// ---------------------------------------------------------------------------
extern "C" void kernel_launch(void* const* d_in, const int* in_sizes, int n_in,
                              void* d_out, int out_size)
{
    const float* x           = (const float*)d_in[0];
    const float* w_qkv       = (const float*)d_in[1];
    const float* w_dw        = (const float*)d_in[2];
    const float* temperature = (const float*)d_in[3];
    const float* mlp_w       = (const float*)d_in[4];
    const float* mlp_b       = (const float*)d_in[5];
    const float* proj_w      = (const float*)d_in[6];
    const float* proj_b      = (const float*)d_in[7];
    float* out = (float*)d_out;

    float *qkv1, *winb, *att;
    cudaGetSymbolAddress((void**)&qkv1, g_qkv1);
    cudaGetSymbolAddress((void**)&winb, g_win);
    cudaGetSymbolAddress((void**)&att, g_att);

    cudaFuncSetAttribute(k_attn, cudaFuncAttributeMaxDynamicSharedMemorySize, SMA_TOTAL);

    k_gemm_mma<<<dim3(HW / 256, C3 / 64, BATCH), 256>>>(w_qkv, x, qkv1, nullptr, C3);
    k_dwconv<<<dim3(IMG / 32, IMG / 8, BATCH * C3), dim3(32, 8)>>>(qkv1, w_dw, winb);
    k_attn<<<NWIN, 256, SMA_TOTAL>>>(winb, temperature, mlp_w, mlp_b, att);
    k_gemm_mma<<<dim3(HW / 256, C_IN / 64, BATCH), 256>>>(proj_w, att, out, proj_b, C_IN);
}

// round 10
// speedup vs baseline: 2.4127x; 1.1268x over previous
#include <cuda_runtime.h>
#include <cuda_bf16.h>
#include <math.h>
#include <stdint.h>

// ---------------- problem constants ----------------
#define BATCH 2
#define C_IN 192
#define C3 576
#define HW 65536
#define IMG 256
#define HEADS 6
#define CH 32
#define WS 8
#define NTOK 64
#define NWIN 2048

__device__ float g_qkv1[(size_t)BATCH * C3 * HW];
__device__ float g_win[(size_t)3 * NWIN * HEADS * CH * NTOK];
__device__ float g_att[(size_t)BATCH * C_IN * HW];

// ---------------------------------------------------------------------------
// bf16 helpers (pair-packed b32: low 16 = even-k, high 16 = odd-k)
// ---------------------------------------------------------------------------
__device__ __forceinline__ void split2(float e0, float e1, uint32_t& hp, uint32_t& lp)
{
    __nv_bfloat16 h0 = __float2bfloat16(e0);
    __nv_bfloat16 h1 = __float2bfloat16(e1);
    __nv_bfloat16 l0 = __float2bfloat16(e0 - __bfloat162float(h0));
    __nv_bfloat16 l1 = __float2bfloat16(e1 - __bfloat162float(h1));
    __nv_bfloat162 hh; hh.x = h0; hh.y = h1;
    __nv_bfloat162 ll; ll.x = l0; ll.y = l1;
    hp = *reinterpret_cast<uint32_t*>(&hh);
    lp = *reinterpret_cast<uint32_t*>(&ll);
}

__device__ __forceinline__ uint32_t pack_hi(float e0, float e1)
{
    __nv_bfloat162 hh; hh.x = __float2bfloat16(e0); hh.y = __float2bfloat16(e1);
    return *reinterpret_cast<uint32_t*>(&hh);
}

__device__ __forceinline__ void mma16816(float* d, const uint32_t* a, uint32_t b0, uint32_t b1)
{
    asm volatile(
        "mma.sync.aligned.m16n8k16.row.col.f32.bf16.bf16.f32 "
        "{%0,%1,%2,%3}, {%4,%5,%6,%7}, {%8,%9}, {%0,%1,%2,%3};"
        : "+f"(d[0]), "+f"(d[1]), "+f"(d[2]), "+f"(d[3])
        : "r"(a[0]), "r"(a[1]), "r"(a[2]), "r"(a[3]), "r"(b0), "r"(b1));
}

// ---------------------------------------------------------------------------
// K1/K4: GEMM Y[o,p] = sum_c W[o,c] * X[c,p] (+bias), K=192, bf16-split MMA.
// CTA tile 64(M) x 256(N) x 32(K); 8 warps in 2x4; warp tile 32x64.
// launch_bounds(256,2): cap regs at 128 so TWO CTAs are resident per SM —
// their pack and MMA phases interleave, hiding latency of both.
// ---------------------------------------------------------------------------
__global__ __launch_bounds__(256, 2) void k_gemm_mma(
    const float* __restrict__ Wt, const float* __restrict__ Xall,
    float* __restrict__ Yall, const float* __restrict__ bias, int M)
{
    const float* X = Xall + (size_t)blockIdx.z * C_IN * HW;
    float* Y = Yall + (size_t)blockIdx.z * (size_t)M * HW;
    const int oTile = blockIdx.y * 64;
    const int pTile = blockIdx.x * 256;

    __shared__ uint32_t WsH[2][64][9], WsL[2][64][9];
    __shared__ uint32_t XsH[2][256][9], XsL[2][256][9];

    const int tid = threadIdx.x;
    const int lane = tid & 31;
    const int wid = tid >> 5;
    const int warpM = wid >> 2;     // 0..1 -> rows warpM*32
    const int warpN = wid & 3;      // 0..3 -> cols warpN*64
    const int g = lane >> 2;        // 0..7
    const int t = lane & 3;         // 0..3

    float acc[2][8][4];
#pragma unroll
    for (int im = 0; im < 2; im++)
#pragma unroll
        for (int jn = 0; jn < 8; jn++)
#pragma unroll
            for (int r = 0; r < 4; r++) acc[im][jn][r] = 0.f;

    const int wo = tid >> 2;            // 0..63 : W row in tile
    const int wsub = tid & 3;           // 0..3  : 8-k chunk

    for (int k0 = 0; k0 < 192; k0 += 32) {
        // ---- W tile (64 x 32), float4 loads, pair-packed stores ----
        {
            const float* wptr = &Wt[(size_t)(oTile + wo) * 192 + k0 + wsub * 8];
            float4 f0 = *(const float4*)wptr;
            float4 f1 = *(const float4*)(wptr + 4);
            float f[8] = {f0.x, f0.y, f0.z, f0.w, f1.x, f1.y, f1.z, f1.w};
#pragma unroll
            for (int j = 0; j < 4; j++) {
                uint32_t hp, lp;
                split2(f[2 * j], f[2 * j + 1], hp, lp);
                int kk2 = wsub * 4 + j;
                int ch = kk2 >> 3, cc = kk2 & 7;
                WsH[ch][wo][cc] = hp;
                WsL[ch][wo][cc] = lp;
            }
        }
        // ---- X tile (32 x 256): conflict-free pack stores ----
        {
#pragma unroll
            for (int it = 0; it < 2; it++) {
                int kp = (tid >> 5) + it * 8;       // 0..15
                int ch = kp >> 3, cc = kp & 7;
                const float* r0 = X + (size_t)(k0 + 2 * kp) * HW + pTile + lane;
#pragma unroll
                for (int pm = 0; pm < 8; pm++) {
                    float f0 = r0[pm * 32];
                    float f1 = r0[pm * 32 + HW];
                    uint32_t hp, lp;
                    split2(f0, f1, hp, lp);
                    XsH[ch][lane + 32 * pm][cc] = hp;
                    XsL[ch][lane + 32 * pm][cc] = lp;
                }
            }
        }
        __syncthreads();

#pragma unroll
        for (int ch = 0; ch < 2; ch++) {
            uint32_t Ah[2][4], Al[2][4];
#pragma unroll
            for (int im = 0; im < 2; im++) {
                int r0 = warpM * 32 + im * 16 + g;
                Ah[im][0] = WsH[ch][r0][t];
                Ah[im][1] = WsH[ch][r0 + 8][t];
                Ah[im][2] = WsH[ch][r0][t + 4];
                Ah[im][3] = WsH[ch][r0 + 8][t + 4];
                Al[im][0] = WsL[ch][r0][t];
                Al[im][1] = WsL[ch][r0 + 8][t];
                Al[im][2] = WsL[ch][r0][t + 4];
                Al[im][3] = WsL[ch][r0 + 8][t + 4];
            }
#pragma unroll
            for (int jn = 0; jn < 8; jn++) {
                int col = warpN * 64 + jn * 8 + g;
                uint32_t bh0 = XsH[ch][col][t], bh1 = XsH[ch][col][t + 4];
                uint32_t bl0 = XsL[ch][col][t], bl1 = XsL[ch][col][t + 4];
#pragma unroll
                for (int im = 0; im < 2; im++) {
                    mma16816(acc[im][jn], Al[im], bh0, bh1);
                    mma16816(acc[im][jn], Ah[im], bl0, bl1);
                    mma16816(acc[im][jn], Ah[im], bh0, bh1);
                }
            }
        }
        __syncthreads();
    }

    // ---- epilogue ----
#pragma unroll
    for (int im = 0; im < 2; im++) {
        int row = oTile + warpM * 32 + im * 16 + g;
        float bs0 = bias ? bias[row] : 0.f;
        float bs1 = bias ? bias[row + 8] : 0.f;
#pragma unroll
        for (int jn = 0; jn < 8; jn++) {
            int col = pTile + warpN * 64 + jn * 8 + t * 2;
            float2 r0 = make_float2(acc[im][jn][0] + bs0, acc[im][jn][1] + bs0);
            float2 r1 = make_float2(acc[im][jn][2] + bs1, acc[im][jn][3] + bs1);
            *(float2*)&Y[(size_t)row * HW + col] = r0;
            *(float2*)&Y[(size_t)(row + 8) * HW + col] = r1;
        }
    }
}

// ---------------------------------------------------------------------------
// K2: depthwise 3x3 (zero pad 1) + scatter into window layout
// ---------------------------------------------------------------------------
__global__ __launch_bounds__(256) void k_dwconv(
    const float* __restrict__ in, const float* __restrict__ wd,
    float* __restrict__ outWin)
{
    const int plane = blockIdx.z;
    const int b = plane / C3, ch3 = plane - b * C3;
    const int x0 = blockIdx.x * 32, y0 = blockIdx.y * 8;

    __shared__ float sm[10][34];
    const float* P = in + (size_t)plane * HW;
    const int tx = threadIdx.x, ty = threadIdx.y;
    const int lt = ty * 32 + tx;

    for (int e = lt; e < 340; e += 256) {
        int r = e / 34, cc = e - r * 34;
        int gy = y0 - 1 + r, gx = x0 - 1 + cc;
        float v = 0.f;
        if (gy >= 0 && gy < IMG && gx >= 0 && gx < IMG) v = P[gy * IMG + gx];
        sm[r][cc] = v;
    }
    __syncthreads();

    const float* wp = wd + ch3 * 9;
    float s = wp[0] * sm[ty + 0][tx + 0] + wp[1] * sm[ty + 0][tx + 1] + wp[2] * sm[ty + 0][tx + 2]
            + wp[3] * sm[ty + 1][tx + 0] + wp[4] * sm[ty + 1][tx + 1] + wp[5] * sm[ty + 1][tx + 2]
            + wp[6] * sm[ty + 2][tx + 0] + wp[7] * sm[ty + 2][tx + 1] + wp[8] * sm[ty + 2][tx + 2];

    const int h = y0 + ty, w = x0 + tx;
    const int z = ch3 / 192;
    const int head = (ch3 % 192) >> 5;
    const int c = ch3 & 31;
    const int win = b * 1024 + (h >> 3) * 32 + (w >> 3);
    const int tok = ((h & 7) << 3) + (w & 7);
    size_t dst = ((((size_t)z * NWIN + win) * HEADS + head) * CH + c) * NTOK + tok;
    outWin[dst] = s;
}

// ---------------------------------------------------------------------------
// K3 (register MMA): one block per window, 8 warps, loops 6 heads.
// Cross-head prefetch: q/k/v gmem loads for head h+1 are issued right after
// head h's pack stores; results consumed at the next iteration top.
// ---------------------------------------------------------------------------
#define SMA_MWH 0
#define SMA_MWL 8448
#define SMA_QH 16896
#define SMA_KH 21120
#define SMA_VPH 25344
#define SMA_VPL 29568
#define SMA_VTH 33792
#define SMA_VTL 38144
#define SMA_VS  42496
#define SMA_AS  42496
#define SMA_AH  51200
#define SMA_AL  53376
#define SMA_MBS 55552
#define SMA_TOTAL 55808

__global__ __launch_bounds__(256) void k_attn(
    const float* __restrict__ winBuf, const float* __restrict__ temperature,
    const float* __restrict__ mlp_w, const float* __restrict__ mlp_b,
    float* __restrict__ out)
{
    extern __shared__ char smraw[];
    uint32_t* mwh = (uint32_t*)(smraw + SMA_MWH);
    uint32_t* mwl = (uint32_t*)(smraw + SMA_MWL);
    uint32_t* qh  = (uint32_t*)(smraw + SMA_QH);
    uint32_t* kh  = (uint32_t*)(smraw + SMA_KH);
    uint32_t* vph = (uint32_t*)(smraw + SMA_VPH);
    uint32_t* vpl = (uint32_t*)(smraw + SMA_VPL);
    uint32_t* vth = (uint32_t*)(smraw + SMA_VTH);
    uint32_t* vtl = (uint32_t*)(smraw + SMA_VTL);
    float*    vsf = (float*)(smraw + SMA_VS);
    float*    As  = (float*)(smraw + SMA_AS);
    uint32_t* Ahs = (uint32_t*)(smraw + SMA_AH);
    uint32_t* Als = (uint32_t*)(smraw + SMA_AL);
    float*    mbs = (float*)(smraw + SMA_MBS);

    const int winId = blockIdx.x;
    const int tid = threadIdx.x;
    const int lane = tid & 31;
    const int wid = tid >> 5;
    const int g = lane >> 2;
    const int t = lane & 3;
    const int mi = wid >> 2;
    const int ni = wid & 3;

    const size_t zs = (size_t)NWIN * HEADS * CH * NTOK;

    {
        int y = tid >> 2, pp0 = (tid & 3) * 8;
        const float* p = mlp_w + y * 64 + pp0 * 2;
        float4 f0 = *(const float4*)p;
        float4 f1 = *(const float4*)(p + 4);
        float4 f2 = *(const float4*)(p + 8);
        float4 f3 = *(const float4*)(p + 12);
        float f[16] = {f0.x, f0.y, f0.z, f0.w, f1.x, f1.y, f1.z, f1.w,
                       f2.x, f2.y, f2.z, f2.w, f3.x, f3.y, f3.z, f3.w};
#pragma unroll
        for (int i = 0; i < 8; i++) {
            uint32_t hp, lp;
            split2(f[2 * i], f[2 * i + 1], hp, lp);
            mwh[y * 33 + pp0 + i] = hp;
            mwl[y * 33 + pp0 + i] = lp;
        }
    }
    if (tid < 64) mbs[tid] = mlp_b[tid];

    const int rr = tid >> 3;
    const int seg = tid & 7;

    const int bb = winId >> 10, rem = winId & 1023;
    const int h1 = rem >> 5, w1 = rem & 31;

    // loop-carried q/k/v registers (prefetched one head ahead)
    float fq[8], fk[8], fv[8];
    {
        const size_t base0 = (size_t)(winId * HEADS) * (CH * NTOK);
        const float* pq = winBuf + base0 + rr * 64 + seg * 8;
        float4 a = *(const float4*)pq;
        float4 b = *(const float4*)(pq + 4);
        fq[0]=a.x; fq[1]=a.y; fq[2]=a.z; fq[3]=a.w; fq[4]=b.x; fq[5]=b.y; fq[6]=b.z; fq[7]=b.w;
        const float* pk = winBuf + zs + base0 + rr * 64 + seg * 8;
        a = *(const float4*)pk; b = *(const float4*)(pk + 4);
        fk[0]=a.x; fk[1]=a.y; fk[2]=a.z; fk[3]=a.w; fk[4]=b.x; fk[5]=b.y; fk[6]=b.z; fk[7]=b.w;
        const float* pv = winBuf + 2 * zs + base0 + rr * 64 + seg * 8;
        a = *(const float4*)pv; b = *(const float4*)(pv + 4);
        fv[0]=a.x; fv[1]=a.y; fv[2]=a.z; fv[3]=a.w; fv[4]=b.x; fv[5]=b.y; fv[6]=b.z; fv[7]=b.w;
    }

    for (int head = 0; head < HEADS; head++) {
        __syncthreads();   // (a) smem regions free from previous head

        // ---- q: norm + hi-pack from registers ----
        {
            float ss = 0.f;
#pragma unroll
            for (int i = 0; i < 8; i++) ss += fq[i] * fq[i];
            ss += __shfl_xor_sync(0xffffffffu, ss, 1);
            ss += __shfl_xor_sync(0xffffffffu, ss, 2);
            ss += __shfl_xor_sync(0xffffffffu, ss, 4);
            float inv = 1.0f / fmaxf(sqrtf(ss), 1e-12f);
#pragma unroll
            for (int i = 0; i < 4; i++)
                qh[rr * 33 + seg * 4 + i] = pack_hi(fq[2 * i] * inv, fq[2 * i + 1] * inv);
        }
        // ---- k: norm + hi-pack ----
        {
            float ss = 0.f;
#pragma unroll
            for (int i = 0; i < 8; i++) ss += fk[i] * fk[i];
            ss += __shfl_xor_sync(0xffffffffu, ss, 1);
            ss += __shfl_xor_sync(0xffffffffu, ss, 2);
            ss += __shfl_xor_sync(0xffffffffu, ss, 4);
            float inv = 1.0f / fmaxf(sqrtf(ss), 1e-12f);
#pragma unroll
            for (int i = 0; i < 4; i++)
                kh[rr * 33 + seg * 4 + i] = pack_hi(fk[2 * i] * inv, fk[2 * i + 1] * inv);
        }
        // ---- v: split-pack + fp32 stage ----
        {
#pragma unroll
            for (int i = 0; i < 4; i++) {
                uint32_t hp, lp;
                split2(fv[2 * i], fv[2 * i + 1], hp, lp);
                vph[rr * 33 + seg * 4 + i] = hp;
                vpl[rr * 33 + seg * 4 + i] = lp;
            }
            *(float4*)&vsf[rr * 68 + seg * 8] = make_float4(fv[0], fv[1], fv[2], fv[3]);
            *(float4*)&vsf[rr * 68 + seg * 8 + 4] = make_float4(fv[4], fv[5], fv[6], fv[7]);
        }
        // ---- prefetch next head into registers (consumed next iteration) ----
        if (head + 1 < HEADS) {
            const size_t basen = (size_t)(winId * HEADS + head + 1) * (CH * NTOK);
            const float* pq = winBuf + basen + rr * 64 + seg * 8;
            float4 a = *(const float4*)pq;
            float4 b = *(const float4*)(pq + 4);
            fq[0]=a.x; fq[1]=a.y; fq[2]=a.z; fq[3]=a.w; fq[4]=b.x; fq[5]=b.y; fq[6]=b.z; fq[7]=b.w;
            const float* pk = winBuf + zs + basen + rr * 64 + seg * 8;
            a = *(const float4*)pk; b = *(const float4*)(pk + 4);
            fk[0]=a.x; fk[1]=a.y; fk[2]=a.z; fk[3]=a.w; fk[4]=b.x; fk[5]=b.y; fk[6]=b.z; fk[7]=b.w;
            const float* pv = winBuf + 2 * zs + basen + rr * 64 + seg * 8;
            a = *(const float4*)pv; b = *(const float4*)(pv + 4);
            fv[0]=a.x; fv[1]=a.y; fv[2]=a.z; fv[3]=a.w; fv[4]=b.x; fv[5]=b.y; fv[6]=b.z; fv[7]=b.w;
        }
        __syncthreads();   // (b) packs + vsf visible

        // ---- build v^T pairs over d ----
        {
            int x = tid >> 2;
            int dpb = tid & 3;
#pragma unroll
            for (int i = 0; i < 4; i++) {
                int dp = dpb + 4 * i;
                float e0 = vsf[(2 * dp) * 68 + x];
                float e1 = vsf[(2 * dp + 1) * 68 + x];
                uint32_t hp, lp;
                split2(e0, e1, hp, lp);
                vth[x * 17 + dp] = hp;
                vtl[x * 17 + dp] = lp;
            }
        }
        __syncthreads();   // (c)

        // ---- QK^T (hi-only) ----
        {
            float cacc[4] = {0.f, 0.f, 0.f, 0.f};
#pragma unroll
            for (int c = 0; c < 4; c++) {
                int p0 = c * 8 + t, p1 = p0 + 4;
                uint32_t A[4];
                A[0] = qh[(mi * 16 + g) * 33 + p0];
                A[1] = qh[(mi * 16 + g + 8) * 33 + p0];
                A[2] = qh[(mi * 16 + g) * 33 + p1];
                A[3] = qh[(mi * 16 + g + 8) * 33 + p1];
                uint32_t b0 = kh[(ni * 8 + g) * 33 + p0];
                uint32_t b1 = kh[(ni * 8 + g) * 33 + p1];
                mma16816(cacc, A, b0, b1);
            }
            const float temp = temperature[head];
            As[(mi * 16 + g) * 36 + ni * 8 + 2 * t] = cacc[0] * temp;
            As[(mi * 16 + g) * 36 + ni * 8 + 2 * t + 1] = cacc[1] * temp;
            As[(mi * 16 + g + 8) * 36 + ni * 8 + 2 * t] = cacc[2] * temp;
            As[(mi * 16 + g + 8) * 36 + ni * 8 + 2 * t + 1] = cacc[3] * temp;
        }
        __syncthreads();   // (d)

        // ---- softmax; emit split pairs ----
        {
            int r = tid >> 3, j0 = (tid & 7) * 4;
            float4 v4 = *(const float4*)&As[r * 36 + j0];
            float v[4] = {v4.x, v4.y, v4.z, v4.w};
            float m = fmaxf(fmaxf(v[0], v[1]), fmaxf(v[2], v[3]));
            m = fmaxf(m, __shfl_xor_sync(0xffffffffu, m, 1));
            m = fmaxf(m, __shfl_xor_sync(0xffffffffu, m, 2));
            m = fmaxf(m, __shfl_xor_sync(0xffffffffu, m, 4));
            float s = 0.f;
#pragma unroll
            for (int i = 0; i < 4; i++) { v[i] = __expf(v[i] - m); s += v[i]; }
            s += __shfl_xor_sync(0xffffffffu, s, 1);
            s += __shfl_xor_sync(0xffffffffu, s, 2);
            s += __shfl_xor_sync(0xffffffffu, s, 4);
            float inv = 1.0f / s;
            int jp = (tid & 7) * 2;
            uint32_t hp, lp;
            split2(v[0] * inv, v[1] * inv, hp, lp);
            Ahs[r * 17 + jp] = hp; Als[r * 17 + jp] = lp;
            split2(v[2] * inv, v[3] * inv, hp, lp);
            Ahs[r * 17 + jp + 1] = hp; Als[r * 17 + jp + 1] = lp;
        }
        __syncthreads();   // (e)

        // ---- A·V and V·mlp_w^T; fused epilogue ----
        {
            float oa[2][4], ga[2][4];
#pragma unroll
            for (int nt = 0; nt < 2; nt++)
#pragma unroll
                for (int r = 0; r < 4; r++) { oa[nt][r] = 0.f; ga[nt][r] = 0.f; }

#pragma unroll
            for (int c = 0; c < 2; c++) {
                int p0 = c * 8 + t, p1 = p0 + 4;
                uint32_t Ahf[4], Alf[4];
                Ahf[0] = Ahs[(mi * 16 + g) * 17 + p0];
                Ahf[1] = Ahs[(mi * 16 + g + 8) * 17 + p0];
                Ahf[2] = Ahs[(mi * 16 + g) * 17 + p1];
                Ahf[3] = Ahs[(mi * 16 + g + 8) * 17 + p1];
                Alf[0] = Als[(mi * 16 + g) * 17 + p0];
                Alf[1] = Als[(mi * 16 + g + 8) * 17 + p0];
                Alf[2] = Als[(mi * 16 + g) * 17 + p1];
                Alf[3] = Als[(mi * 16 + g + 8) * 17 + p1];
#pragma unroll
                for (int nt = 0; nt < 2; nt++) {
                    int n = (ni * 2 + nt) * 8 + g;
                    uint32_t bh0 = vth[n * 17 + p0], bh1 = vth[n * 17 + p1];
                    uint32_t bl0 = vtl[n * 17 + p0], bl1 = vtl[n * 17 + p1];
                    mma16816(oa[nt], Ahf, bl0, bl1);
                    mma16816(oa[nt], Alf, bh0, bh1);
                    mma16816(oa[nt], Ahf, bh0, bh1);
                }
            }
#pragma unroll
            for (int c = 0; c < 4; c++) {
                int p0 = c * 8 + t, p1 = p0 + 4;
                uint32_t Vh[4], Vl[4];
                Vh[0] = vph[(mi * 16 + g) * 33 + p0];
                Vh[1] = vph[(mi * 16 + g + 8) * 33 + p0];
                Vh[2] = vph[(mi * 16 + g) * 33 + p1];
                Vh[3] = vph[(mi * 16 + g + 8) * 33 + p1];
                Vl[0] = vpl[(mi * 16 + g) * 33 + p0];
                Vl[1] = vpl[(mi * 16 + g + 8) * 33 + p0];
                Vl[2] = vpl[(mi * 16 + g) * 33 + p1];
                Vl[3] = vpl[(mi * 16 + g + 8) * 33 + p1];
#pragma unroll
                for (int nt = 0; nt < 2; nt++) {
                    int n = (ni * 2 + nt) * 8 + g;
                    uint32_t bh0 = mwh[n * 33 + p0], bh1 = mwh[n * 33 + p1];
                    uint32_t bl0 = mwl[n * 33 + p0], bl1 = mwl[n * 33 + p1];
                    mma16816(ga[nt], Vh, bl0, bl1);
                    mma16816(ga[nt], Vl, bh0, bh1);
                    mma16816(ga[nt], Vh, bh0, bh1);
                }
            }
#pragma unroll
            for (int nt = 0; nt < 2; nt++) {
                int ntok = ni * 2 + nt;
                float b0 = mbs[ntok * 8 + 2 * t];
                float b1 = mbs[ntok * 8 + 2 * t + 1];
#pragma unroll
                for (int half = 0; half < 2; half++) {
                    int row = mi * 16 + g + half * 8;
                    float o0 = oa[nt][half * 2], o1 = oa[nt][half * 2 + 1];
                    float x0 = ga[nt][half * 2] + b0;
                    float x1 = ga[nt][half * 2 + 1] + b1;
                    float ge0 = 0.5f * x0 * (1.0f + erff(x0 * 0.70710678118654752f));
                    float ge1 = 0.5f * x1 * (1.0f + erff(x1 * 0.70710678118654752f));
                    size_t addr = ((((size_t)bb * C_IN + head * CH + row) * IMG
                                    + h1 * 8 + ntok) * IMG) + w1 * 8 + 2 * t;
                    *(float2*)&out[addr] = make_float2(o0 * ge0, o1 * ge1);
                }
            }
        }
    }
}

// ---------------------------------------------------------------------------
extern "C" void kernel_launch(void* const* d_in, const int* in_sizes, int n_in,
                              void* d_out, int out_size)
{
    const float* x           = (const float*)d_in[0];
    const float* w_qkv       = (const float*)d_in[1];
    const float* w_dw        = (const float*)d_in[2];
    const float* temperature = (const float*)d_in[3];
    const float* mlp_w       = (const float*)d_in[4];
    const float* mlp_b       = (const float*)d_in[5];
    const float* proj_w      = (const float*)d_in[6];
    const float* proj_b      = (const float*)d_in[7];
    float* out = (float*)d_out;

    float *qkv1, *winb, *att;
    cudaGetSymbolAddress((void**)&qkv1, g_qkv1);
    cudaGetSymbolAddress((void**)&winb, g_win);
    cudaGetSymbolAddress((void**)&att, g_att);

    cudaFuncSetAttribute(k_attn, cudaFuncAttributeMaxDynamicSharedMemorySize, SMA_TOTAL);

    k_gemm_mma<<<dim3(HW / 256, C3 / 64, BATCH), 256>>>(w_qkv, x, qkv1, nullptr, C3);
    k_dwconv<<<dim3(IMG / 32, IMG / 8, BATCH * C3), dim3(32, 8)>>>(qkv1, w_dw, winb);
    k_attn<<<NWIN, 256, SMA_TOTAL>>>(winb, temperature, mlp_w, mlp_b, att);
    k_gemm_mma<<<dim3(HW / 256, C_IN / 64, BATCH), 256>>>(proj_w, att, out, proj_b, C_IN);
}